// round 12
// baseline (speedup 1.0000x reference)
#include <cuda_runtime.h>
#include <cuda_bf16.h>
#include <math.h>
#include <stdint.h>

// ---------------- constants ----------------
constexpr int B_ = 8, S_ = 2048, D_ = 320, NH_ = 5, HD_ = 64, FF_ = 864, NL_ = 6, NLOOPS_ = 8;
constexpr int KSEL = 1638;
constexpr int T_ = B_ * S_;
constexpr int MS_ = B_ * KSEL;

constexpr size_t WOFF_QKV = 0;
constexpr size_t WOFF_WO  = 307200;
constexpr size_t WOFF_GU  = 409600;   // interleaved gate/up rows, 2*FF x D
constexpr size_t WOFF_D   = 962560;
constexpr size_t LW       = 1239040;
constexpr size_t WTOT     = LW * NL_;

// ---------------- scratch ----------------
__device__ float g_x[T_ * D_];
__device__ float g_probs[T_];
__device__ int   g_selidx[MS_];
__device__ float g_selprob[MS_];
__device__ float g_cos[S_ * 32];
__device__ float g_sin[S_ * 32];

__device__ __nv_bfloat16 g_whi[WTOT],       g_wlo[WTOT];
__device__ __nv_bfloat16 g_hhi[T_ * D_],    g_hlo[T_ * D_];
__device__ __nv_bfloat16 g_athi[T_ * D_],   g_atlo[T_ * D_];
__device__ __nv_bfloat16 g_hshi[MS_ * D_],  g_hslo[MS_ * D_];
__device__ __nv_bfloat16 g_acthi[MS_ * FF_],g_actlo[MS_ * FF_];

// attention operand buffers (head-major): [B*NH][S][HD]
__device__ __nv_bfloat16 g_qh[T_ * D_], g_ql[T_ * D_];
__device__ __nv_bfloat16 g_kh[T_ * D_], g_kl[T_ * D_];
__device__ __nv_bfloat16 g_vth[T_ * D_], g_vtl[T_ * D_];   // [bh][d][S]

__device__ __forceinline__ void split_bf(float f, __nv_bfloat16& h, __nv_bfloat16& l) {
    h = __float2bfloat16(f);
    l = __float2bfloat16(f - __bfloat162float(h));
}
__device__ __forceinline__ uint32_t pack2(__nv_bfloat16 a, __nv_bfloat16 b) {
    return ((uint32_t)*(uint16_t*)&a) | ((uint32_t)*(uint16_t*)&b << 16);
}

#define LDSM4(R0, R1, R2, R3, ADDR) \
    asm volatile("ldmatrix.sync.aligned.m8n8.x4.shared.b16 {%0,%1,%2,%3}, [%4];" \
                 : "=r"(R0), "=r"(R1), "=r"(R2), "=r"(R3) : "r"(ADDR))

#define MMA16816(d, a, b) asm volatile( \
    "mma.sync.aligned.m16n8k16.row.col.f32.bf16.bf16.f32 " \
    "{%0,%1,%2,%3},{%4,%5,%6,%7},{%8,%9},{%0,%1,%2,%3};\n" \
    : "+f"(d[0]), "+f"(d[1]), "+f"(d[2]), "+f"(d[3]) \
    : "r"(a[0]), "r"(a[1]), "r"(a[2]), "r"(a[3]), "r"(b[0]), "r"(b[1]))

// ---------------- rope tables ----------------
__global__ void ropetab_k() {
    int s = blockIdx.x, i = threadIdx.x;
    double freq = exp(-(double)i * (log(10000.0) / 32.0));
    double a = (double)s * freq;
    g_cos[s * 32 + i] = (float)cos(a);
    g_sin[s * 32 + i] = (float)sin(a);
}

// ---------------- embedding ----------------
__global__ void embed_k(const int* __restrict__ ids, const int* __restrict__ iter,
                        const float* __restrict__ emb, const float* __restrict__ iter_emb) {
    int t = blockIdx.x, d = threadIdx.x;
    int id = ids[t];
    float v = emb[(size_t)id * D_ + d];
    int it = iter[0];
    if (it < NLOOPS_) v += iter_emb[it * D_ + d];
    g_x[(size_t)t * D_ + d] = v;
}

// ---------------- weight conversion (gate/up interleaved) ----------------
__global__ void cvt_all_k(const float* __restrict__ Wqkv, const float* __restrict__ wo,
                          const float* __restrict__ gate, const float* __restrict__ up,
                          const float* __restrict__ down) {
    size_t i = (size_t)blockIdx.x * 256 + threadIdx.x;
    if (i >= WTOT) return;
    size_t l = i / LW, off = i % LW;
    const float* src; size_t so;
    if (off < WOFF_WO)      { src = Wqkv; so = l * 307200 + off; }
    else if (off < WOFF_GU) { src = wo;   so = l * 102400 + (off - WOFF_WO); }
    else if (off < WOFF_D)  {
        size_t idx = off - WOFF_GU;
        size_t row = idx / D_, col = idx % D_;
        size_t ff = row >> 1;
        src = (row & 1) ? up : gate;
        so = l * 276480 + ff * D_ + col;
    }
    else                    { src = down; so = l * 276480 + (off - WOFF_D); }
    float f = src[so];
    __nv_bfloat16 h, lo; split_bf(f, h, lo);
    g_whi[i] = h; g_wlo[i] = lo;
}

// ---------------- rmsnorm variants ----------------
__global__ void rmsnorm_k(const float* __restrict__ in, const float* __restrict__ w,
                          float* __restrict__ out, int nrows) {
    int warp = (blockIdx.x * blockDim.x + threadIdx.x) >> 5;
    int lane = threadIdx.x & 31;
    if (warp >= nrows) return;
    const float* r = in + (size_t)warp * D_;
    float e[10]; float ss = 0.f;
#pragma unroll
    for (int i = 0; i < 10; i++) { e[i] = r[lane + 32 * i]; ss += e[i] * e[i]; }
#pragma unroll
    for (int o = 16; o > 0; o >>= 1) ss += __shfl_xor_sync(0xffffffffu, ss, o);
    float rr = rsqrtf(ss * (1.0f / D_) + 1e-6f);
    float* po = out + (size_t)warp * D_;
#pragma unroll
    for (int i = 0; i < 10; i++) po[lane + 32 * i] = e[i] * rr * w[lane + 32 * i];
}

// also zeroes g_probs[row] for the fused-router atomic accumulation
__global__ void rmsnorm_bf_k(const float* __restrict__ in, const float* __restrict__ w,
                             __nv_bfloat16* __restrict__ ohi, __nv_bfloat16* __restrict__ olo,
                             int nrows) {
    int warp = (blockIdx.x * blockDim.x + threadIdx.x) >> 5;
    int lane = threadIdx.x & 31;
    if (warp >= nrows) return;
    if (lane == 0) g_probs[warp] = 0.f;
    const float* r = in + (size_t)warp * D_;
    float e[10]; float ss = 0.f;
#pragma unroll
    for (int i = 0; i < 10; i++) { e[i] = r[lane + 32 * i]; ss += e[i] * e[i]; }
#pragma unroll
    for (int o = 16; o > 0; o >>= 1) ss += __shfl_xor_sync(0xffffffffu, ss, o);
    float rr = rsqrtf(ss * (1.0f / D_) + 1e-6f);
#pragma unroll
    for (int i = 0; i < 10; i++) {
        float v = e[i] * rr * w[lane + 32 * i];
        __nv_bfloat16 h, l; split_bf(v, h, l);
        ohi[(size_t)warp * D_ + lane + 32 * i] = h;
        olo[(size_t)warp * D_ + lane + 32 * i] = l;
    }
}

__global__ void gather_rmsnorm_k(const float* __restrict__ in, const float* __restrict__ w,
                                 __nv_bfloat16* __restrict__ ohi, __nv_bfloat16* __restrict__ olo) {
    int warp = (blockIdx.x * blockDim.x + threadIdx.x) >> 5;
    int lane = threadIdx.x & 31;
    if (warp >= MS_) return;
    int b = warp / KSEL;
    int tok = g_selidx[warp];
    const float* r = in + (size_t)(b * S_ + tok) * D_;
    float e[10]; float ss = 0.f;
#pragma unroll
    for (int i = 0; i < 10; i++) { e[i] = r[lane + 32 * i]; ss += e[i] * e[i]; }
#pragma unroll
    for (int o = 16; o > 0; o >>= 1) ss += __shfl_xor_sync(0xffffffffu, ss, o);
    float rr = rsqrtf(ss * (1.0f / D_) + 1e-6f);
#pragma unroll
    for (int i = 0; i < 10; i++) {
        float v = e[i] * rr * w[lane + 32 * i];
        __nv_bfloat16 h, l; split_bf(v, h, l);
        ohi[(size_t)warp * D_ + lane + 32 * i] = h;
        olo[(size_t)warp * D_ + lane + 32 * i] = l;
    }
}

// =====================================================================
// bf16x3 tensor-core GEMM, templated on WN: BN = 64*WN.
// WN=2: 2-stage/2-sync. WN=1: 3-stage/1-sync. occupancy 2 both.
// epi: 0 store, 1 += C (+ fused router partial-dot if rw), 2 scatter-add,
//      3 fused qkv rope/split/pack, 4 fused gate/up silu
// =====================================================================
template <int WN>
__global__ __launch_bounds__(256, 2) void hgemm3_k(
    const __nv_bfloat16* __restrict__ Ahi, const __nv_bfloat16* __restrict__ Alo,
    const __nv_bfloat16* __restrict__ Bhi, const __nv_bfloat16* __restrict__ Blo,
    float* __restrict__ C, int M, int N, int K, int epi,
    const int* __restrict__ selidx, const float* __restrict__ selprob,
    float* __restrict__ xout, const float* __restrict__ rw) {
    extern __shared__ __nv_bfloat16 sm[];
    constexpr int BN  = 64 * WN;
    constexpr int MT  = WN;
    constexpr int ASZ = 128 * 40;
    constexpr int BSZ = BN * 40;
    constexpr int STG = 2 * ASZ + 2 * BSZ;
    constexpr int NSTG = (WN == 1) ? 3 : 2;

    const int tid = threadIdx.x;
    const int lane = tid & 31, warp = tid >> 5;
    const int wn = warp & (WN - 1);
    const int wm = warp / WN;
    const int bm = blockIdx.y * 128, bn = blockIdx.x * BN;

    float acc[MT][8][4];
#pragma unroll
    for (int a = 0; a < MT; a++)
#pragma unroll
        for (int b = 0; b < 8; b++)
#pragma unroll
            for (int c = 0; c < 4; c++) acc[a][b][c] = 0.f;

    uint32_t smemBase = (uint32_t)__cvta_generic_to_shared(sm);
    const int KT = K / 32;
    const int crow = tid >> 2, cseg = tid & 3;

    auto load_stage = [&](int kt, int s) {
        int k0 = kt * 32;
#pragma unroll
        for (int arr = 0; arr < 4; arr++) {
            const __nv_bfloat16* src = arr == 0 ? Ahi : arr == 1 ? Alo : arr == 2 ? Bhi : Blo;
            const bool isA = arr < 2;
            const int lim = isA ? M : N;
            const int gbase = isA ? bm : bn;
            const int nIter = isA ? 2 : BN / 64;
            const uint32_t abase = (arr < 2) ? (uint32_t)(arr * ASZ)
                                             : (uint32_t)(2 * ASZ + (arr - 2) * BSZ);
#pragma unroll
            for (int i = 0; i < 2; i++) {
                if (i >= nIter) break;
                int row = crow + i * 64;
                int g = gbase + row;
                const __nv_bfloat16* gp = src + (size_t)g * K + k0 + cseg * 8;
                uint32_t dst = smemBase + (uint32_t)(s * STG + abase + row * 40 + cseg * 8) * 2u;
                int sz = (g < lim) ? 16 : 0;
                asm volatile("cp.async.cg.shared.global [%0], [%1], 16, %2;\n"
                             :: "r"(dst), "l"(gp), "r"(sz));
            }
        }
        asm volatile("cp.async.commit_group;\n");
    };

    const uint32_t arow = ((lane >> 3) & 1) * 8 + (lane & 7);
    const uint32_t acolo = (lane >> 4) * 8;
    const uint32_t brow = (lane >> 4) * 8 + (lane & 7);
    const uint32_t bcolo = ((lane >> 3) & 1) * 8;

    auto compute = [&](int s) {
        const uint32_t base = smemBase + (uint32_t)(s * STG) * 2u;
#pragma unroll
        for (int kk = 0; kk < 2; kk++) {
            const uint32_t k0 = kk * 16;
            uint32_t ah[MT][4], al[MT][4];
#pragma unroll
            for (int mt = 0; mt < MT; mt++) {
                uint32_t aoff = (uint32_t)((wm * 16 * MT + mt * 16 + arow) * 40 + k0 + acolo) * 2u;
                LDSM4(ah[mt][0], ah[mt][1], ah[mt][2], ah[mt][3], base + aoff);
                LDSM4(al[mt][0], al[mt][1], al[mt][2], al[mt][3], base + ASZ * 2u + aoff);
            }
#pragma unroll
            for (int p = 0; p < 4; p++) {
                uint32_t boff = (uint32_t)((wn * 64 + p * 16 + brow) * 40 + k0 + bcolo) * 2u;
                uint32_t bhf[2][2], blf[2][2];
                LDSM4(bhf[0][0], bhf[0][1], bhf[1][0], bhf[1][1], base + 2u * ASZ * 2u + boff);
                LDSM4(blf[0][0], blf[0][1], blf[1][0], blf[1][1],
                      base + (2u * ASZ + BSZ) * 2u + boff);
#pragma unroll
                for (int q = 0; q < 2; q++) {
                    const int nt = 2 * p + q;
#pragma unroll
                    for (int mt = 0; mt < MT; mt++) {
                        MMA16816(acc[mt][nt], ah[mt], bhf[q]);
                        MMA16816(acc[mt][nt], ah[mt], blf[q]);
                        MMA16816(acc[mt][nt], al[mt], bhf[q]);
                    }
                }
            }
        }
    };

    if (NSTG == 3) {
        load_stage(0, 0);
        if (KT > 1) load_stage(1, 1);
        for (int kt = 0; kt < KT; kt++) {
            if (kt + 1 < KT) asm volatile("cp.async.wait_group 1;\n");
            else             asm volatile("cp.async.wait_group 0;\n");
            __syncthreads();
            if (kt + 2 < KT) load_stage(kt + 2, (kt + 2) % 3);
            compute(kt % 3);
        }
    } else {
        load_stage(0, 0);
        if (KT > 1) load_stage(1, 1);
        for (int kt = 0; kt < KT; kt++) {
            const int s = kt & 1;
            if (kt + 1 < KT) asm volatile("cp.async.wait_group 1;\n");
            else             asm volatile("cp.async.wait_group 0;\n");
            __syncthreads();
            compute(s);
            __syncthreads();
            if (kt + 2 < KT) load_stage(kt + 2, s);
        }
    }

    // ---------------- epilogues ----------------
    if (epi == 3) {
        int nb = (bn + wn * 64) >> 6;
        if (nb < 15) {
            int region = nb / 5, hd = nb % 5;
#pragma unroll
            for (int mt = 0; mt < MT; mt++) {
#pragma unroll
                for (int ci = 0; ci < 2; ci++) {
                    int m = bm + wm * 16 * MT + mt * 16 + (lane >> 2) + ci * 8;
                    if (m >= M) continue;
                    int b = m / S_, s = m - b * S_;
                    size_t bh_ = (size_t)(b * NH_ + hd);
                    if (region < 2) {
                        __nv_bfloat16* dh = (region ? g_kh : g_qh) + (bh_ * S_ + s) * HD_;
                        __nv_bfloat16* dl = (region ? g_kl : g_ql) + (bh_ * S_ + s) * HD_;
#pragma unroll
                        for (int nt = 0; nt < 4; nt++) {
                            int d0 = nt * 8 + (lane & 3) * 2;
                            float r1[2], r2[2];
#pragma unroll
                            for (int j = 0; j < 2; j++) {
                                int dd = d0 + j;
                                float v1 = acc[mt][nt][ci * 2 + j];
                                float v2 = acc[mt][nt + 4][ci * 2 + j];
                                float co = g_cos[s * 32 + dd];
                                float si = g_sin[s * 32 + dd];
                                r1[j] = v1 * co - v2 * si;
                                r2[j] = v2 * co + v1 * si;
                            }
                            __nv_bfloat16 h0, l0, h1, l1;
                            split_bf(r1[0], h0, l0); split_bf(r1[1], h1, l1);
                            *(uint32_t*)(dh + d0) = pack2(h0, h1);
                            *(uint32_t*)(dl + d0) = pack2(l0, l1);
                            split_bf(r2[0], h0, l0); split_bf(r2[1], h1, l1);
                            *(uint32_t*)(dh + d0 + 32) = pack2(h0, h1);
                            *(uint32_t*)(dl + d0 + 32) = pack2(l0, l1);
                        }
                    } else {
#pragma unroll
                        for (int nt = 0; nt < 8; nt++) {
#pragma unroll
                            for (int j = 0; j < 2; j++) {
                                int d = nt * 8 + (lane & 3) * 2 + j;
                                float v = acc[mt][nt][ci * 2 + j];
                                __nv_bfloat16 hh, ll; split_bf(v, hh, ll);
                                size_t idx = (bh_ * HD_ + d) * S_ + s;
                                g_vth[idx] = hh;
                                g_vtl[idx] = ll;
                            }
                        }
                    }
                }
            }
        }
    } else if (epi == 4) {
#pragma unroll
        for (int mt = 0; mt < MT; mt++) {
#pragma unroll
            for (int ci = 0; ci < 2; ci++) {
                int m = bm + wm * 16 * MT + mt * 16 + (lane >> 2) + ci * 8;
                if (m >= M) continue;
#pragma unroll
                for (int nt = 0; nt < 8; nt++) {
                    int n = bn + wn * 64 + nt * 8 + (lane & 3) * 2;
                    if (n + 1 < N) {
                        float gv = acc[mt][nt][ci * 2 + 0];
                        float uv = acc[mt][nt][ci * 2 + 1];
                        float v = gv / (1.f + __expf(-gv)) * uv;
                        int ff = n >> 1;
                        __nv_bfloat16 h, l; split_bf(v, h, l);
                        g_acthi[(size_t)m * FF_ + ff] = h;
                        g_actlo[(size_t)m * FF_ + ff] = l;
                    }
                }
            }
        }
    } else {
#pragma unroll
        for (int mt = 0; mt < MT; mt++) {
#pragma unroll
            for (int ci = 0; ci < 2; ci++) {
                int m = bm + wm * 16 * MT + mt * 16 + (lane >> 2) + ci * 8;
                if (m >= M) continue;
                int xrow = 0; float sc = 0.f;
                if (epi == 2) { xrow = (m / KSEL) * S_ + selidx[m]; sc = selprob[m]; }
                float zp = 0.f;
#pragma unroll
                for (int nt = 0; nt < 8; nt++) {
                    int n = bn + wn * 64 + nt * 8 + (lane & 3) * 2;
                    float v0 = acc[mt][nt][ci * 2 + 0];
                    float v1 = acc[mt][nt][ci * 2 + 1];
                    if (n + 1 < N) {
                        if (epi == 0) {
                            *(float2*)(C + (size_t)m * N + n) = make_float2(v0, v1);
                        } else if (epi == 1) {
                            float2 c = *(float2*)(C + (size_t)m * N + n);
                            c.x += v0; c.y += v1;
                            *(float2*)(C + (size_t)m * N + n) = c;
                            if (rw) {
                                float2 w2 = *(const float2*)(rw + n);
                                zp += c.x * w2.x + c.y * w2.y;
                            }
                        } else {
                            float2 c = *(float2*)(xout + (size_t)xrow * D_ + n);
                            c.x += v0 * sc; c.y += v1 * sc;
                            *(float2*)(xout + (size_t)xrow * D_ + n) = c;
                        }
                    } else if (n < N) {
                        if (epi == 0) C[(size_t)m * N + n] = v0;
                        else if (epi == 1) C[(size_t)m * N + n] += v0;
                        else xout[(size_t)xrow * D_ + n] += v0 * sc;
                    }
                }
                if (epi == 1 && rw) {
                    zp += __shfl_xor_sync(0xffffffffu, zp, 1);
                    zp += __shfl_xor_sync(0xffffffffu, zp, 2);
                    if ((lane & 3) == 0) atomicAdd(&g_probs[m], zp);
                }
            }
        }
    }
}

// =====================================================================
// tensor-core flash attention: 256 threads, 128-row qtiles, heavy-first,
// 3-stage cp.async with ONE __syncthreads per tile.
// =====================================================================
__global__ __launch_bounds__(256, 1) void attn_tc_k() {
    extern __shared__ __nv_bfloat16 asm_[];
    constexpr int RP = 72;
    constexpr int TSZ = 64 * RP;
    constexpr int STG = 4 * TSZ;

    const int bh = blockIdx.x;
    const int qtile = (S_ / 128 - 1) - blockIdx.y;   // heavy tiles first
    const int b = bh / NH_, h = bh % NH_;
    const int tid = threadIdx.x, lane = tid & 31, warp = tid >> 5;
    const int q0 = qtile * 128 + warp * 16;
    const int r1 = lane >> 2, c0 = (lane & 3) * 2;

    uint32_t qh[4][4], ql[4][4];
    {
        const __nv_bfloat16* Qh = g_qh + ((size_t)bh * S_ + q0) * HD_;
        const __nv_bfloat16* Ql = g_ql + ((size_t)bh * S_ + q0) * HD_;
#pragma unroll
        for (int ks = 0; ks < 4; ks++) {
            int kc = ks * 16 + c0;
            qh[ks][0] = *(const uint32_t*)(Qh + r1 * 64 + kc);
            qh[ks][1] = *(const uint32_t*)(Qh + (r1 + 8) * 64 + kc);
            qh[ks][2] = *(const uint32_t*)(Qh + r1 * 64 + kc + 8);
            qh[ks][3] = *(const uint32_t*)(Qh + (r1 + 8) * 64 + kc + 8);
            ql[ks][0] = *(const uint32_t*)(Ql + r1 * 64 + kc);
            ql[ks][1] = *(const uint32_t*)(Ql + (r1 + 8) * 64 + kc);
            ql[ks][2] = *(const uint32_t*)(Ql + r1 * 64 + kc + 8);
            ql[ks][3] = *(const uint32_t*)(Ql + (r1 + 8) * 64 + kc + 8);
        }
    }

    float oacc[8][4];
#pragma unroll
    for (int i = 0; i < 8; i++)
#pragma unroll
        for (int j = 0; j < 4; j++) oacc[i][j] = 0.f;
    float m1 = -1e30f, m2 = -1e30f, l1 = 0.f, l2 = 0.f;

    uint32_t smemBase = (uint32_t)__cvta_generic_to_shared(asm_);
    const int NT = 2 * qtile + 2;
    const int lrow = tid >> 2, lch = tid & 3;
    const uint32_t frow = (lane >> 4) * 8 + (lane & 7);
    const uint32_t fcolo = ((lane >> 3) & 1) * 8;

    auto load_tile = [&](int kt, int st) {
        int k0 = kt * 64;
        const __nv_bfloat16* srcs[4] = {
            g_kh + ((size_t)bh * S_ + k0) * HD_,
            g_kl + ((size_t)bh * S_ + k0) * HD_,
            g_vth + (size_t)bh * HD_ * S_ + k0,
            g_vtl + (size_t)bh * HD_ * S_ + k0};
        const size_t rstride[4] = {HD_, HD_, S_, S_};
#pragma unroll
        for (int arr = 0; arr < 4; arr++) {
#pragma unroll
            for (int i = 0; i < 2; i++) {
                int ch = lch + i * 4;
                const __nv_bfloat16* gp = srcs[arr] + (size_t)lrow * rstride[arr] + ch * 8;
                uint32_t dst = smemBase + (uint32_t)(st * STG + arr * TSZ + lrow * RP + ch * 8) * 2u;
                asm volatile("cp.async.cg.shared.global [%0], [%1], 16;\n" :: "r"(dst), "l"(gp));
            }
        }
        asm volatile("cp.async.commit_group;\n");
    };

    load_tile(0, 0);
    if (NT > 1) load_tile(1, 1);
    for (int kt = 0; kt < NT; kt++) {
        if (kt + 1 < NT) asm volatile("cp.async.wait_group 1;\n");
        else             asm volatile("cp.async.wait_group 0;\n");
        __syncthreads();
        if (kt + 2 < NT) load_tile(kt + 2, (kt + 2) % 3);
        const int k0 = kt * 64;
        if (k0 <= q0 + 15) {
            const int st = kt % 3;
            const uint32_t kbase_h = smemBase + (uint32_t)(st * STG) * 2u;
            const uint32_t kbase_l = kbase_h + (uint32_t)TSZ * 2u;
            const uint32_t vbase_h = kbase_h + 2u * (uint32_t)TSZ * 2u;
            const uint32_t vbase_l = kbase_h + 3u * (uint32_t)TSZ * 2u;

            float sacc[8][4];
#pragma unroll
            for (int i = 0; i < 8; i++)
#pragma unroll
                for (int j = 0; j < 4; j++) sacc[i][j] = 0.f;

#pragma unroll
            for (int ks = 0; ks < 4; ks++) {
                const uint32_t kc = ks * 16 + fcolo;
#pragma unroll
                for (int p = 0; p < 4; p++) {
                    uint32_t boff = (uint32_t)((p * 16 + frow) * RP + kc) * 2u;
                    uint32_t kh2[2][2], kl2[2][2];
                    LDSM4(kh2[0][0], kh2[0][1], kh2[1][0], kh2[1][1], kbase_h + boff);
                    LDSM4(kl2[0][0], kl2[0][1], kl2[1][0], kl2[1][1], kbase_l + boff);
#pragma unroll
                    for (int q = 0; q < 2; q++) {
                        MMA16816(sacc[2 * p + q], qh[ks], kh2[q]);
                        MMA16816(sacc[2 * p + q], qh[ks], kl2[q]);
                        MMA16816(sacc[2 * p + q], ql[ks], kh2[q]);
                    }
                }
            }
            const bool diag = (k0 + 63 > q0);
#pragma unroll
            for (int nt = 0; nt < 8; nt++)
#pragma unroll
                for (int j = 0; j < 4; j++) sacc[nt][j] *= 0.125f;
            if (diag) {
#pragma unroll
                for (int nt = 0; nt < 8; nt++) {
#pragma unroll
                    for (int j = 0; j < 4; j++) {
                        int col = k0 + nt * 8 + c0 + (j & 1);
                        int row = q0 + r1 + ((j >= 2) ? 8 : 0);
                        if (col > row) sacc[nt][j] = -1e30f;
                    }
                }
            }
            float t1 = -1e30f, t2 = -1e30f;
#pragma unroll
            for (int nt = 0; nt < 8; nt++) {
                t1 = fmaxf(t1, fmaxf(sacc[nt][0], sacc[nt][1]));
                t2 = fmaxf(t2, fmaxf(sacc[nt][2], sacc[nt][3]));
            }
            t1 = fmaxf(t1, __shfl_xor_sync(0xffffffffu, t1, 1));
            t1 = fmaxf(t1, __shfl_xor_sync(0xffffffffu, t1, 2));
            t2 = fmaxf(t2, __shfl_xor_sync(0xffffffffu, t2, 1));
            t2 = fmaxf(t2, __shfl_xor_sync(0xffffffffu, t2, 2));
            float nm1 = fmaxf(m1, t1), nm2 = fmaxf(m2, t2);
            float cc1 = __expf(m1 - nm1), cc2 = __expf(m2 - nm2);
            l1 *= cc1; l2 *= cc2;
#pragma unroll
            for (int nt = 0; nt < 8; nt++) {
                oacc[nt][0] *= cc1; oacc[nt][1] *= cc1;
                oacc[nt][2] *= cc2; oacc[nt][3] *= cc2;
            }
            m1 = nm1; m2 = nm2;
            float rs1 = 0.f, rs2 = 0.f;
#pragma unroll
            for (int nt = 0; nt < 8; nt++) {
                sacc[nt][0] = __expf(sacc[nt][0] - nm1); rs1 += sacc[nt][0];
                sacc[nt][1] = __expf(sacc[nt][1] - nm1); rs1 += sacc[nt][1];
                sacc[nt][2] = __expf(sacc[nt][2] - nm2); rs2 += sacc[nt][2];
                sacc[nt][3] = __expf(sacc[nt][3] - nm2); rs2 += sacc[nt][3];
            }
            rs1 += __shfl_xor_sync(0xffffffffu, rs1, 1);
            rs1 += __shfl_xor_sync(0xffffffffu, rs1, 2);
            rs2 += __shfl_xor_sync(0xffffffffu, rs2, 1);
            rs2 += __shfl_xor_sync(0xffffffffu, rs2, 2);
            l1 += rs1; l2 += rs2;
            uint32_t pa[4][4], pl[4][4];
#pragma unroll
            for (int kp = 0; kp < 4; kp++) {
                int n0 = 2 * kp, n1 = 2 * kp + 1;
#define PPACK(dsti, x0, x1) { \
                float a0 = (x0), a1 = (x1); \
                __nv_bfloat16 b0 = __float2bfloat16(a0), b1 = __float2bfloat16(a1); \
                pa[kp][dsti] = ((uint32_t)*(uint16_t*)&b0) | ((uint32_t)*(uint16_t*)&b1 << 16); \
                float r0 = a0 - __bfloat162float(b0), r1f = a1 - __bfloat162float(b1); \
                __nv_bfloat16 c0b = __float2bfloat16(r0), c1b = __float2bfloat16(r1f); \
                pl[kp][dsti] = ((uint32_t)*(uint16_t*)&c0b) | ((uint32_t)*(uint16_t*)&c1b << 16); }
                PPACK(0, sacc[n0][0], sacc[n0][1]);
                PPACK(1, sacc[n0][2], sacc[n0][3]);
                PPACK(2, sacc[n1][0], sacc[n1][1]);
                PPACK(3, sacc[n1][2], sacc[n1][3]);
#undef PPACK
            }
#pragma unroll
            for (int kp = 0; kp < 4; kp++) {
                const uint32_t kc = kp * 16 + fcolo;
#pragma unroll
                for (int p = 0; p < 4; p++) {
                    uint32_t boff = (uint32_t)((p * 16 + frow) * RP + kc) * 2u;
                    uint32_t vh2[2][2], vl2[2][2];
                    LDSM4(vh2[0][0], vh2[0][1], vh2[1][0], vh2[1][1], vbase_h + boff);
                    LDSM4(vl2[0][0], vl2[0][1], vl2[1][0], vl2[1][1], vbase_l + boff);
#pragma unroll
                    for (int q = 0; q < 2; q++) {
                        MMA16816(oacc[2 * p + q], pa[kp], vh2[q]);
                        MMA16816(oacc[2 * p + q], pa[kp], vl2[q]);
                        MMA16816(oacc[2 * p + q], pl[kp], vh2[q]);
                    }
                }
            }
        }
    }

    float inv1 = 1.f / l1, inv2 = 1.f / l2;
    int row1 = b * S_ + q0 + r1;
    int row2 = row1 + 8;
#pragma unroll
    for (int nt = 0; nt < 8; nt++) {
        int col = h * HD_ + nt * 8 + c0;
        {
            float v0 = oacc[nt][0] * inv1, v1 = oacc[nt][1] * inv1;
            __nv_bfloat16 h0, l0, h1v, l1v;
            split_bf(v0, h0, l0); split_bf(v1, h1v, l1v);
            *(uint32_t*)(g_athi + (size_t)row1 * D_ + col) = pack2(h0, h1v);
            *(uint32_t*)(g_atlo + (size_t)row1 * D_ + col) = pack2(l0, l1v);
        }
        {
            float v0 = oacc[nt][2] * inv2, v1 = oacc[nt][3] * inv2;
            __nv_bfloat16 h0, l0, h1v, l1v;
            split_bf(v0, h0, l0); split_bf(v1, h1v, l1v);
            *(uint32_t*)(g_athi + (size_t)row2 * D_ + col) = pack2(h0, h1v);
            *(uint32_t*)(g_atlo + (size_t)row2 * D_ + col) = pack2(l0, l1v);
        }
    }
}

// ---------------- exact top-k (z -> sigmoid, monotonic) ----------------
__global__ __launch_bounds__(512) void topk_k() {
    int b = blockIdx.x;
    __shared__ float p[S_];
    for (int i = threadIdx.x; i < S_; i += 512) {
        float z = g_probs[b * S_ + i];
        p[i] = 1.f / (1.f + __expf(-z));
    }
    __syncthreads();
    int idx[4]; float v[4]; int cnt[4];
#pragma unroll
    for (int t = 0; t < 4; t++) {
        idx[t] = threadIdx.x + t * 512;
        v[t] = p[idx[t]];
        cnt[t] = 0;
    }
    for (int j = 0; j < S_; j++) {
        float pj = p[j];
#pragma unroll
        for (int t = 0; t < 4; t++)
            cnt[t] += (pj > v[t]) || (pj == v[t] && j < idx[t]) ? 1 : 0;
    }
#pragma unroll
    for (int t = 0; t < 4; t++) {
        if (cnt[t] < KSEL) {
            g_selidx[b * KSEL + cnt[t]] = idx[t];
            g_selprob[b * KSEL + cnt[t]] = v[t];
        }
    }
}

// ---------------- host launch ----------------
extern "C" void kernel_launch(void* const* d_in, const int* in_sizes, int n_in,
                              void* d_out, int out_size) {
    const int* ids            = (const int*)d_in[0];
    const int* iter           = (const int*)d_in[1];
    const float* emb          = (const float*)d_in[2];
    const float* iter_emb     = (const float*)d_in[3];
    const float* attn_norm_w  = (const float*)d_in[4];
    const float* Wqkv         = (const float*)d_in[5];
    const float* wo_w         = (const float*)d_in[6];
    const float* router_w     = (const float*)d_in[7];
    const float* mlp_norm_w   = (const float*)d_in[8];
    const float* gate_w       = (const float*)d_in[9];
    const float* up_w         = (const float*)d_in[10];
    const float* down_w       = (const float*)d_in[11];
    const float* final_norm_w = (const float*)d_in[12];
    float* out = (float*)d_out;

    float *px, *pselprob;
    int* pselidx;
    __nv_bfloat16 *pwhi, *pwlo, *phhi, *phlo, *pathi, *patlo, *phshi, *phslo, *pacthi, *pactlo;
    cudaGetSymbolAddress((void**)&px, g_x);
    cudaGetSymbolAddress((void**)&pselidx, g_selidx);
    cudaGetSymbolAddress((void**)&pselprob, g_selprob);
    cudaGetSymbolAddress((void**)&pwhi, g_whi);
    cudaGetSymbolAddress((void**)&pwlo, g_wlo);
    cudaGetSymbolAddress((void**)&phhi, g_hhi);
    cudaGetSymbolAddress((void**)&phlo, g_hlo);
    cudaGetSymbolAddress((void**)&pathi, g_athi);
    cudaGetSymbolAddress((void**)&patlo, g_atlo);
    cudaGetSymbolAddress((void**)&phshi, g_hshi);
    cudaGetSymbolAddress((void**)&phslo, g_hslo);
    cudaGetSymbolAddress((void**)&pacthi, g_acthi);
    cudaGetSymbolAddress((void**)&pactlo, g_actlo);

    constexpr int SMEM_G2 = 2 * (2 * 128 * 40 + 2 * 128 * 40) * 2;  // 81920 B (WN=2, 2 stages)
    constexpr int SMEM_G1 = 3 * (2 * 128 * 40 + 2 * 64 * 40) * 2;   // 92160 B (WN=1, 3 stages)
    constexpr int SMEM_ATTN = 3 * 4 * 64 * 72 * 2;                  // 110592 B (3 stages)
    cudaFuncSetAttribute(hgemm3_k<2>, cudaFuncAttributeMaxDynamicSharedMemorySize, SMEM_G2);
    cudaFuncSetAttribute(hgemm3_k<1>, cudaFuncAttributeMaxDynamicSharedMemorySize, SMEM_G1);
    cudaFuncSetAttribute(attn_tc_k, cudaFuncAttributeMaxDynamicSharedMemorySize, SMEM_ATTN);

    ropetab_k<<<S_, 32>>>();
    embed_k<<<T_, D_>>>(ids, iter, emb, iter_emb);
    cvt_all_k<<<(int)((WTOT + 255) / 256), 256>>>(Wqkv, wo_w, gate_w, up_w, down_w);

    const int MT  = T_ / 128;                 // 128
    const int MTS = (MS_ + 127) / 128;        // 103

    for (int l = 0; l < NL_; l++) {
        size_t lo = (size_t)l * LW;

        rmsnorm_bf_k<<<T_ / 4, 128>>>(px, attn_norm_w + l * D_, phhi, phlo, T_);
        // qkv GEMM with fused rope/split/pack epilogue (WN=1: N=960=15x64 exact)
        {
            dim3 g(15, MT);
            hgemm3_k<1><<<g, 256, SMEM_G1>>>(phhi, phlo, pwhi + lo + WOFF_QKV, pwlo + lo + WOFF_QKV,
                                             nullptr, T_, 3 * D_, D_, 3, nullptr, nullptr, nullptr,
                                             nullptr);
        }
        {
            dim3 g(B_ * NH_, S_ / 128);
            attn_tc_k<<<g, 256, SMEM_ATTN>>>();
        }
        // x += attn @ wo^T, fused router partial-dot (WN=1)
        {
            dim3 g((D_ + 63) / 64, MT);
            hgemm3_k<1><<<g, 256, SMEM_G1>>>(pathi, patlo, pwhi + lo + WOFF_WO, pwlo + lo + WOFF_WO,
                                             px, T_, D_, D_, 1, nullptr, nullptr, nullptr,
                                             router_w + l * D_);
        }
        topk_k<<<B_, 512>>>();
        gather_rmsnorm_k<<<(MS_ + 3) / 4, 128>>>(px, mlp_norm_w + l * D_, phshi, phslo);
        // fused gate+up GEMM (interleaved N=1728) with silu*up epilogue (WN=2)
        {
            dim3 g((2 * FF_ + 127) / 128, MTS);
            hgemm3_k<2><<<g, 256, SMEM_G2>>>(phshi, phslo, pwhi + lo + WOFF_GU, pwlo + lo + WOFF_GU,
                                             nullptr, MS_, 2 * FF_, D_, 4, nullptr, nullptr, nullptr,
                                             nullptr);
        }
        // x[sel] += (act @ down^T) * prob (WN=1)
        {
            dim3 g((D_ + 63) / 64, MTS);
            hgemm3_k<1><<<g, 256, SMEM_G1>>>(pacthi, pactlo, pwhi + lo + WOFF_D, pwlo + lo + WOFF_D,
                                             nullptr, MS_, D_, FF_, 2, pselidx, pselprob, px,
                                             nullptr);
        }
    }

    rmsnorm_k<<<T_ / 4, 128>>>(px, final_norm_w, out, T_);
}

// round 13
// speedup vs baseline: 1.0111x; 1.0111x over previous
#include <cuda_runtime.h>
#include <cuda_bf16.h>
#include <math.h>
#include <stdint.h>

// ---------------- constants ----------------
constexpr int B_ = 8, S_ = 2048, D_ = 320, NH_ = 5, HD_ = 64, FF_ = 864, NL_ = 6, NLOOPS_ = 8;
constexpr int KSEL = 1638;
constexpr int T_ = B_ * S_;
constexpr int MS_ = B_ * KSEL;

constexpr size_t WOFF_QKV = 0;
constexpr size_t WOFF_WO  = 307200;
constexpr size_t WOFF_GU  = 409600;   // interleaved gate/up rows, 2*FF x D
constexpr size_t WOFF_D   = 962560;
constexpr size_t LW       = 1239040;
constexpr size_t WTOT     = LW * NL_;

// ---------------- scratch ----------------
__device__ float g_x[T_ * D_];
__device__ float g_probs[T_];
__device__ int   g_selidx[MS_];
__device__ float g_selprob[MS_];
__device__ float g_cos[S_ * 32];
__device__ float g_sin[S_ * 32];

__device__ __nv_bfloat16 g_whi[WTOT],       g_wlo[WTOT];
__device__ __nv_bfloat16 g_hhi[T_ * D_],    g_hlo[T_ * D_];
__device__ __nv_bfloat16 g_athi[T_ * D_],   g_atlo[T_ * D_];
__device__ __nv_bfloat16 g_hshi[MS_ * D_],  g_hslo[MS_ * D_];
__device__ __nv_bfloat16 g_acthi[MS_ * FF_],g_actlo[MS_ * FF_];

// attention operand buffers (head-major): [B*NH][S][HD]
__device__ __nv_bfloat16 g_qh[T_ * D_], g_ql[T_ * D_];
__device__ __nv_bfloat16 g_kh[T_ * D_], g_kl[T_ * D_];
__device__ __nv_bfloat16 g_vth[T_ * D_], g_vtl[T_ * D_];   // [bh][d][S]

__device__ __forceinline__ void split_bf(float f, __nv_bfloat16& h, __nv_bfloat16& l) {
    h = __float2bfloat16(f);
    l = __float2bfloat16(f - __bfloat162float(h));
}
__device__ __forceinline__ uint32_t pack2(__nv_bfloat16 a, __nv_bfloat16 b) {
    return ((uint32_t)*(uint16_t*)&a) | ((uint32_t)*(uint16_t*)&b << 16);
}

#define LDSM4(R0, R1, R2, R3, ADDR) \
    asm volatile("ldmatrix.sync.aligned.m8n8.x4.shared.b16 {%0,%1,%2,%3}, [%4];" \
                 : "=r"(R0), "=r"(R1), "=r"(R2), "=r"(R3) : "r"(ADDR))

#define MMA16816(d, a, b) asm volatile( \
    "mma.sync.aligned.m16n8k16.row.col.f32.bf16.bf16.f32 " \
    "{%0,%1,%2,%3},{%4,%5,%6,%7},{%8,%9},{%0,%1,%2,%3};\n" \
    : "+f"(d[0]), "+f"(d[1]), "+f"(d[2]), "+f"(d[3]) \
    : "r"(a[0]), "r"(a[1]), "r"(a[2]), "r"(a[3]), "r"(b[0]), "r"(b[1]))

// ---------------- rope tables ----------------
__global__ void ropetab_k() {
    int s = blockIdx.x, i = threadIdx.x;
    double freq = exp(-(double)i * (log(10000.0) / 32.0));
    double a = (double)s * freq;
    g_cos[s * 32 + i] = (float)cos(a);
    g_sin[s * 32 + i] = (float)sin(a);
}

// ---------------- embedding ----------------
__global__ void embed_k(const int* __restrict__ ids, const int* __restrict__ iter,
                        const float* __restrict__ emb, const float* __restrict__ iter_emb) {
    int t = blockIdx.x, d = threadIdx.x;
    int id = ids[t];
    float v = emb[(size_t)id * D_ + d];
    int it = iter[0];
    if (it < NLOOPS_) v += iter_emb[it * D_ + d];
    g_x[(size_t)t * D_ + d] = v;
}

// ---------------- weight conversion (gate/up interleaved) ----------------
__global__ void cvt_all_k(const float* __restrict__ Wqkv, const float* __restrict__ wo,
                          const float* __restrict__ gate, const float* __restrict__ up,
                          const float* __restrict__ down) {
    size_t i = (size_t)blockIdx.x * 256 + threadIdx.x;
    if (i >= WTOT) return;
    size_t l = i / LW, off = i % LW;
    const float* src; size_t so;
    if (off < WOFF_WO)      { src = Wqkv; so = l * 307200 + off; }
    else if (off < WOFF_GU) { src = wo;   so = l * 102400 + (off - WOFF_WO); }
    else if (off < WOFF_D)  {
        size_t idx = off - WOFF_GU;
        size_t row = idx / D_, col = idx % D_;
        size_t ff = row >> 1;
        src = (row & 1) ? up : gate;
        so = l * 276480 + ff * D_ + col;
    }
    else                    { src = down; so = l * 276480 + (off - WOFF_D); }
    float f = src[so];
    __nv_bfloat16 h, lo; split_bf(f, h, lo);
    g_whi[i] = h; g_wlo[i] = lo;
}

// ---------------- rmsnorm variants ----------------
__global__ void rmsnorm_k(const float* __restrict__ in, const float* __restrict__ w,
                          float* __restrict__ out, int nrows) {
    int warp = (blockIdx.x * blockDim.x + threadIdx.x) >> 5;
    int lane = threadIdx.x & 31;
    if (warp >= nrows) return;
    const float* r = in + (size_t)warp * D_;
    float e[10]; float ss = 0.f;
#pragma unroll
    for (int i = 0; i < 10; i++) { e[i] = r[lane + 32 * i]; ss += e[i] * e[i]; }
#pragma unroll
    for (int o = 16; o > 0; o >>= 1) ss += __shfl_xor_sync(0xffffffffu, ss, o);
    float rr = rsqrtf(ss * (1.0f / D_) + 1e-6f);
    float* po = out + (size_t)warp * D_;
#pragma unroll
    for (int i = 0; i < 10; i++) po[lane + 32 * i] = e[i] * rr * w[lane + 32 * i];
}

// also zeroes g_probs[row] for the fused-router atomic accumulation
__global__ void rmsnorm_bf_k(const float* __restrict__ in, const float* __restrict__ w,
                             __nv_bfloat16* __restrict__ ohi, __nv_bfloat16* __restrict__ olo,
                             int nrows) {
    int warp = (blockIdx.x * blockDim.x + threadIdx.x) >> 5;
    int lane = threadIdx.x & 31;
    if (warp >= nrows) return;
    if (lane == 0) g_probs[warp] = 0.f;
    const float* r = in + (size_t)warp * D_;
    float e[10]; float ss = 0.f;
#pragma unroll
    for (int i = 0; i < 10; i++) { e[i] = r[lane + 32 * i]; ss += e[i] * e[i]; }
#pragma unroll
    for (int o = 16; o > 0; o >>= 1) ss += __shfl_xor_sync(0xffffffffu, ss, o);
    float rr = rsqrtf(ss * (1.0f / D_) + 1e-6f);
#pragma unroll
    for (int i = 0; i < 10; i++) {
        float v = e[i] * rr * w[lane + 32 * i];
        __nv_bfloat16 h, l; split_bf(v, h, l);
        ohi[(size_t)warp * D_ + lane + 32 * i] = h;
        olo[(size_t)warp * D_ + lane + 32 * i] = l;
    }
}

__global__ void gather_rmsnorm_k(const float* __restrict__ in, const float* __restrict__ w,
                                 __nv_bfloat16* __restrict__ ohi, __nv_bfloat16* __restrict__ olo) {
    int warp = (blockIdx.x * blockDim.x + threadIdx.x) >> 5;
    int lane = threadIdx.x & 31;
    if (warp >= MS_) return;
    int b = warp / KSEL;
    int tok = g_selidx[warp];
    const float* r = in + (size_t)(b * S_ + tok) * D_;
    float e[10]; float ss = 0.f;
#pragma unroll
    for (int i = 0; i < 10; i++) { e[i] = r[lane + 32 * i]; ss += e[i] * e[i]; }
#pragma unroll
    for (int o = 16; o > 0; o >>= 1) ss += __shfl_xor_sync(0xffffffffu, ss, o);
    float rr = rsqrtf(ss * (1.0f / D_) + 1e-6f);
#pragma unroll
    for (int i = 0; i < 10; i++) {
        float v = e[i] * rr * w[lane + 32 * i];
        __nv_bfloat16 h, l; split_bf(v, h, l);
        ohi[(size_t)warp * D_ + lane + 32 * i] = h;
        olo[(size_t)warp * D_ + lane + 32 * i] = l;
    }
}

// =====================================================================
// bf16x3 tensor-core GEMM, templated on WN: BN = 64*WN.
// WN=2: 2-stage/2-sync. WN=1: 3-stage/1-sync. occupancy 2 both.
// epi: 0 store, 1 += C (+ fused router partial-dot if rw), 2 scatter-add,
//      3 fused qkv rope/split/pack, 4 fused gate/up silu
// =====================================================================
template <int WN>
__global__ __launch_bounds__(256, 2) void hgemm3_k(
    const __nv_bfloat16* __restrict__ Ahi, const __nv_bfloat16* __restrict__ Alo,
    const __nv_bfloat16* __restrict__ Bhi, const __nv_bfloat16* __restrict__ Blo,
    float* __restrict__ C, int M, int N, int K, int epi,
    const int* __restrict__ selidx, const float* __restrict__ selprob,
    float* __restrict__ xout, const float* __restrict__ rw) {
    extern __shared__ __nv_bfloat16 sm[];
    constexpr int BN  = 64 * WN;
    constexpr int MT  = WN;
    constexpr int ASZ = 128 * 40;
    constexpr int BSZ = BN * 40;
    constexpr int STG = 2 * ASZ + 2 * BSZ;
    constexpr int NSTG = (WN == 1) ? 3 : 2;

    const int tid = threadIdx.x;
    const int lane = tid & 31, warp = tid >> 5;
    const int wn = warp & (WN - 1);
    const int wm = warp / WN;
    const int bm = blockIdx.y * 128, bn = blockIdx.x * BN;

    float acc[MT][8][4];
#pragma unroll
    for (int a = 0; a < MT; a++)
#pragma unroll
        for (int b = 0; b < 8; b++)
#pragma unroll
            for (int c = 0; c < 4; c++) acc[a][b][c] = 0.f;

    uint32_t smemBase = (uint32_t)__cvta_generic_to_shared(sm);
    const int KT = K / 32;
    const int crow = tid >> 2, cseg = tid & 3;

    auto load_stage = [&](int kt, int s) {
        int k0 = kt * 32;
#pragma unroll
        for (int arr = 0; arr < 4; arr++) {
            const __nv_bfloat16* src = arr == 0 ? Ahi : arr == 1 ? Alo : arr == 2 ? Bhi : Blo;
            const bool isA = arr < 2;
            const int lim = isA ? M : N;
            const int gbase = isA ? bm : bn;
            const int nIter = isA ? 2 : BN / 64;
            const uint32_t abase = (arr < 2) ? (uint32_t)(arr * ASZ)
                                             : (uint32_t)(2 * ASZ + (arr - 2) * BSZ);
#pragma unroll
            for (int i = 0; i < 2; i++) {
                if (i >= nIter) break;
                int row = crow + i * 64;
                int g = gbase + row;
                const __nv_bfloat16* gp = src + (size_t)g * K + k0 + cseg * 8;
                uint32_t dst = smemBase + (uint32_t)(s * STG + abase + row * 40 + cseg * 8) * 2u;
                int sz = (g < lim) ? 16 : 0;
                asm volatile("cp.async.cg.shared.global [%0], [%1], 16, %2;\n"
                             :: "r"(dst), "l"(gp), "r"(sz));
            }
        }
        asm volatile("cp.async.commit_group;\n");
    };

    const uint32_t arow = ((lane >> 3) & 1) * 8 + (lane & 7);
    const uint32_t acolo = (lane >> 4) * 8;
    const uint32_t brow = (lane >> 4) * 8 + (lane & 7);
    const uint32_t bcolo = ((lane >> 3) & 1) * 8;

    auto compute = [&](int s) {
        const uint32_t base = smemBase + (uint32_t)(s * STG) * 2u;
#pragma unroll
        for (int kk = 0; kk < 2; kk++) {
            const uint32_t k0 = kk * 16;
            uint32_t ah[MT][4], al[MT][4];
#pragma unroll
            for (int mt = 0; mt < MT; mt++) {
                uint32_t aoff = (uint32_t)((wm * 16 * MT + mt * 16 + arow) * 40 + k0 + acolo) * 2u;
                LDSM4(ah[mt][0], ah[mt][1], ah[mt][2], ah[mt][3], base + aoff);
                LDSM4(al[mt][0], al[mt][1], al[mt][2], al[mt][3], base + ASZ * 2u + aoff);
            }
#pragma unroll
            for (int p = 0; p < 4; p++) {
                uint32_t boff = (uint32_t)((wn * 64 + p * 16 + brow) * 40 + k0 + bcolo) * 2u;
                uint32_t bhf[2][2], blf[2][2];
                LDSM4(bhf[0][0], bhf[0][1], bhf[1][0], bhf[1][1], base + 2u * ASZ * 2u + boff);
                LDSM4(blf[0][0], blf[0][1], blf[1][0], blf[1][1],
                      base + (2u * ASZ + BSZ) * 2u + boff);
#pragma unroll
                for (int q = 0; q < 2; q++) {
                    const int nt = 2 * p + q;
#pragma unroll
                    for (int mt = 0; mt < MT; mt++) {
                        MMA16816(acc[mt][nt], ah[mt], bhf[q]);
                        MMA16816(acc[mt][nt], ah[mt], blf[q]);
                        MMA16816(acc[mt][nt], al[mt], bhf[q]);
                    }
                }
            }
        }
    };

    if (NSTG == 3) {
        load_stage(0, 0);
        if (KT > 1) load_stage(1, 1);
        for (int kt = 0; kt < KT; kt++) {
            if (kt + 1 < KT) asm volatile("cp.async.wait_group 1;\n");
            else             asm volatile("cp.async.wait_group 0;\n");
            __syncthreads();
            if (kt + 2 < KT) load_stage(kt + 2, (kt + 2) % 3);
            compute(kt % 3);
        }
    } else {
        load_stage(0, 0);
        if (KT > 1) load_stage(1, 1);
        for (int kt = 0; kt < KT; kt++) {
            const int s = kt & 1;
            if (kt + 1 < KT) asm volatile("cp.async.wait_group 1;\n");
            else             asm volatile("cp.async.wait_group 0;\n");
            __syncthreads();
            compute(s);
            __syncthreads();
            if (kt + 2 < KT) load_stage(kt + 2, s);
        }
    }

    // ---------------- epilogues ----------------
    if (epi == 3) {
        int nb = (bn + wn * 64) >> 6;
        if (nb < 15) {
            int region = nb / 5, hd = nb % 5;
#pragma unroll
            for (int mt = 0; mt < MT; mt++) {
#pragma unroll
                for (int ci = 0; ci < 2; ci++) {
                    int m = bm + wm * 16 * MT + mt * 16 + (lane >> 2) + ci * 8;
                    if (m >= M) continue;
                    int b = m / S_, s = m - b * S_;
                    size_t bh_ = (size_t)(b * NH_ + hd);
                    if (region < 2) {
                        __nv_bfloat16* dh = (region ? g_kh : g_qh) + (bh_ * S_ + s) * HD_;
                        __nv_bfloat16* dl = (region ? g_kl : g_ql) + (bh_ * S_ + s) * HD_;
#pragma unroll
                        for (int nt = 0; nt < 4; nt++) {
                            int d0 = nt * 8 + (lane & 3) * 2;
                            float r1[2], r2[2];
#pragma unroll
                            for (int j = 0; j < 2; j++) {
                                int dd = d0 + j;
                                float v1 = acc[mt][nt][ci * 2 + j];
                                float v2 = acc[mt][nt + 4][ci * 2 + j];
                                float co = g_cos[s * 32 + dd];
                                float si = g_sin[s * 32 + dd];
                                r1[j] = v1 * co - v2 * si;
                                r2[j] = v2 * co + v1 * si;
                            }
                            __nv_bfloat16 h0, l0, h1, l1;
                            split_bf(r1[0], h0, l0); split_bf(r1[1], h1, l1);
                            *(uint32_t*)(dh + d0) = pack2(h0, h1);
                            *(uint32_t*)(dl + d0) = pack2(l0, l1);
                            split_bf(r2[0], h0, l0); split_bf(r2[1], h1, l1);
                            *(uint32_t*)(dh + d0 + 32) = pack2(h0, h1);
                            *(uint32_t*)(dl + d0 + 32) = pack2(l0, l1);
                        }
                    } else {
#pragma unroll
                        for (int nt = 0; nt < 8; nt++) {
#pragma unroll
                            for (int j = 0; j < 2; j++) {
                                int d = nt * 8 + (lane & 3) * 2 + j;
                                float v = acc[mt][nt][ci * 2 + j];
                                __nv_bfloat16 hh, ll; split_bf(v, hh, ll);
                                size_t idx = (bh_ * HD_ + d) * S_ + s;
                                g_vth[idx] = hh;
                                g_vtl[idx] = ll;
                            }
                        }
                    }
                }
            }
        }
    } else if (epi == 4) {
#pragma unroll
        for (int mt = 0; mt < MT; mt++) {
#pragma unroll
            for (int ci = 0; ci < 2; ci++) {
                int m = bm + wm * 16 * MT + mt * 16 + (lane >> 2) + ci * 8;
                if (m >= M) continue;
#pragma unroll
                for (int nt = 0; nt < 8; nt++) {
                    int n = bn + wn * 64 + nt * 8 + (lane & 3) * 2;
                    if (n + 1 < N) {
                        float gv = acc[mt][nt][ci * 2 + 0];
                        float uv = acc[mt][nt][ci * 2 + 1];
                        float v = gv / (1.f + __expf(-gv)) * uv;
                        int ff = n >> 1;
                        __nv_bfloat16 h, l; split_bf(v, h, l);
                        g_acthi[(size_t)m * FF_ + ff] = h;
                        g_actlo[(size_t)m * FF_ + ff] = l;
                    }
                }
            }
        }
    } else {
#pragma unroll
        for (int mt = 0; mt < MT; mt++) {
#pragma unroll
            for (int ci = 0; ci < 2; ci++) {
                int m = bm + wm * 16 * MT + mt * 16 + (lane >> 2) + ci * 8;
                if (m >= M) continue;
                int xrow = 0; float sc = 0.f;
                if (epi == 2) { xrow = (m / KSEL) * S_ + selidx[m]; sc = selprob[m]; }
                float zp = 0.f;
#pragma unroll
                for (int nt = 0; nt < 8; nt++) {
                    int n = bn + wn * 64 + nt * 8 + (lane & 3) * 2;
                    float v0 = acc[mt][nt][ci * 2 + 0];
                    float v1 = acc[mt][nt][ci * 2 + 1];
                    if (n + 1 < N) {
                        if (epi == 0) {
                            *(float2*)(C + (size_t)m * N + n) = make_float2(v0, v1);
                        } else if (epi == 1) {
                            float2 c = *(float2*)(C + (size_t)m * N + n);
                            c.x += v0; c.y += v1;
                            *(float2*)(C + (size_t)m * N + n) = c;
                            if (rw) {
                                float2 w2 = *(const float2*)(rw + n);
                                zp += c.x * w2.x + c.y * w2.y;
                            }
                        } else {
                            float2 c = *(float2*)(xout + (size_t)xrow * D_ + n);
                            c.x += v0 * sc; c.y += v1 * sc;
                            *(float2*)(xout + (size_t)xrow * D_ + n) = c;
                        }
                    } else if (n < N) {
                        if (epi == 0) C[(size_t)m * N + n] = v0;
                        else if (epi == 1) C[(size_t)m * N + n] += v0;
                        else xout[(size_t)xrow * D_ + n] += v0 * sc;
                    }
                }
                if (epi == 1 && rw) {
                    zp += __shfl_xor_sync(0xffffffffu, zp, 1);
                    zp += __shfl_xor_sync(0xffffffffu, zp, 2);
                    if ((lane & 3) == 0) atomicAdd(&g_probs[m], zp);
                }
            }
        }
    }
}

// =====================================================================
// tensor-core flash attention: 256 threads, 128-row qtiles, heavy-first,
// 3-stage cp.async with ONE __syncthreads per tile.
// =====================================================================
__global__ __launch_bounds__(256, 1) void attn_tc_k() {
    extern __shared__ __nv_bfloat16 asm_[];
    constexpr int RP = 72;
    constexpr int TSZ = 64 * RP;
    constexpr int STG = 4 * TSZ;

    const int bh = blockIdx.x;
    const int qtile = (S_ / 128 - 1) - blockIdx.y;   // heavy tiles first
    const int b = bh / NH_, h = bh % NH_;
    const int tid = threadIdx.x, lane = tid & 31, warp = tid >> 5;
    const int q0 = qtile * 128 + warp * 16;
    const int r1 = lane >> 2, c0 = (lane & 3) * 2;

    uint32_t qh[4][4], ql[4][4];
    {
        const __nv_bfloat16* Qh = g_qh + ((size_t)bh * S_ + q0) * HD_;
        const __nv_bfloat16* Ql = g_ql + ((size_t)bh * S_ + q0) * HD_;
#pragma unroll
        for (int ks = 0; ks < 4; ks++) {
            int kc = ks * 16 + c0;
            qh[ks][0] = *(const uint32_t*)(Qh + r1 * 64 + kc);
            qh[ks][1] = *(const uint32_t*)(Qh + (r1 + 8) * 64 + kc);
            qh[ks][2] = *(const uint32_t*)(Qh + r1 * 64 + kc + 8);
            qh[ks][3] = *(const uint32_t*)(Qh + (r1 + 8) * 64 + kc + 8);
            ql[ks][0] = *(const uint32_t*)(Ql + r1 * 64 + kc);
            ql[ks][1] = *(const uint32_t*)(Ql + (r1 + 8) * 64 + kc);
            ql[ks][2] = *(const uint32_t*)(Ql + r1 * 64 + kc + 8);
            ql[ks][3] = *(const uint32_t*)(Ql + (r1 + 8) * 64 + kc + 8);
        }
    }

    float oacc[8][4];
#pragma unroll
    for (int i = 0; i < 8; i++)
#pragma unroll
        for (int j = 0; j < 4; j++) oacc[i][j] = 0.f;
    float m1 = -1e30f, m2 = -1e30f, l1 = 0.f, l2 = 0.f;

    uint32_t smemBase = (uint32_t)__cvta_generic_to_shared(asm_);
    const int NT = 2 * qtile + 2;
    const int lrow = tid >> 2, lch = tid & 3;
    const uint32_t frow = (lane >> 4) * 8 + (lane & 7);
    const uint32_t fcolo = ((lane >> 3) & 1) * 8;

    auto load_tile = [&](int kt, int st) {
        int k0 = kt * 64;
        const __nv_bfloat16* srcs[4] = {
            g_kh + ((size_t)bh * S_ + k0) * HD_,
            g_kl + ((size_t)bh * S_ + k0) * HD_,
            g_vth + (size_t)bh * HD_ * S_ + k0,
            g_vtl + (size_t)bh * HD_ * S_ + k0};
        const size_t rstride[4] = {HD_, HD_, S_, S_};
#pragma unroll
        for (int arr = 0; arr < 4; arr++) {
#pragma unroll
            for (int i = 0; i < 2; i++) {
                int ch = lch + i * 4;
                const __nv_bfloat16* gp = srcs[arr] + (size_t)lrow * rstride[arr] + ch * 8;
                uint32_t dst = smemBase + (uint32_t)(st * STG + arr * TSZ + lrow * RP + ch * 8) * 2u;
                asm volatile("cp.async.cg.shared.global [%0], [%1], 16;\n" :: "r"(dst), "l"(gp));
            }
        }
        asm volatile("cp.async.commit_group;\n");
    };

    load_tile(0, 0);
    if (NT > 1) load_tile(1, 1);
    for (int kt = 0; kt < NT; kt++) {
        if (kt + 1 < NT) asm volatile("cp.async.wait_group 1;\n");
        else             asm volatile("cp.async.wait_group 0;\n");
        __syncthreads();
        if (kt + 2 < NT) load_tile(kt + 2, (kt + 2) % 3);
        const int k0 = kt * 64;
        if (k0 <= q0 + 15) {
            const int st = kt % 3;
            const uint32_t kbase_h = smemBase + (uint32_t)(st * STG) * 2u;
            const uint32_t kbase_l = kbase_h + (uint32_t)TSZ * 2u;
            const uint32_t vbase_h = kbase_h + 2u * (uint32_t)TSZ * 2u;
            const uint32_t vbase_l = kbase_h + 3u * (uint32_t)TSZ * 2u;

            float sacc[8][4];
#pragma unroll
            for (int i = 0; i < 8; i++)
#pragma unroll
                for (int j = 0; j < 4; j++) sacc[i][j] = 0.f;

#pragma unroll
            for (int ks = 0; ks < 4; ks++) {
                const uint32_t kc = ks * 16 + fcolo;
#pragma unroll
                for (int p = 0; p < 4; p++) {
                    uint32_t boff = (uint32_t)((p * 16 + frow) * RP + kc) * 2u;
                    uint32_t kh2[2][2], kl2[2][2];
                    LDSM4(kh2[0][0], kh2[0][1], kh2[1][0], kh2[1][1], kbase_h + boff);
                    LDSM4(kl2[0][0], kl2[0][1], kl2[1][0], kl2[1][1], kbase_l + boff);
#pragma unroll
                    for (int q = 0; q < 2; q++) {
                        MMA16816(sacc[2 * p + q], qh[ks], kh2[q]);
                        MMA16816(sacc[2 * p + q], qh[ks], kl2[q]);
                        MMA16816(sacc[2 * p + q], ql[ks], kh2[q]);
                    }
                }
            }
            const bool diag = (k0 + 63 > q0);
#pragma unroll
            for (int nt = 0; nt < 8; nt++)
#pragma unroll
                for (int j = 0; j < 4; j++) sacc[nt][j] *= 0.125f;
            if (diag) {
#pragma unroll
                for (int nt = 0; nt < 8; nt++) {
#pragma unroll
                    for (int j = 0; j < 4; j++) {
                        int col = k0 + nt * 8 + c0 + (j & 1);
                        int row = q0 + r1 + ((j >= 2) ? 8 : 0);
                        if (col > row) sacc[nt][j] = -1e30f;
                    }
                }
            }
            float t1 = -1e30f, t2 = -1e30f;
#pragma unroll
            for (int nt = 0; nt < 8; nt++) {
                t1 = fmaxf(t1, fmaxf(sacc[nt][0], sacc[nt][1]));
                t2 = fmaxf(t2, fmaxf(sacc[nt][2], sacc[nt][3]));
            }
            t1 = fmaxf(t1, __shfl_xor_sync(0xffffffffu, t1, 1));
            t1 = fmaxf(t1, __shfl_xor_sync(0xffffffffu, t1, 2));
            t2 = fmaxf(t2, __shfl_xor_sync(0xffffffffu, t2, 1));
            t2 = fmaxf(t2, __shfl_xor_sync(0xffffffffu, t2, 2));
            float nm1 = fmaxf(m1, t1), nm2 = fmaxf(m2, t2);
            float cc1 = __expf(m1 - nm1), cc2 = __expf(m2 - nm2);
            l1 *= cc1; l2 *= cc2;
#pragma unroll
            for (int nt = 0; nt < 8; nt++) {
                oacc[nt][0] *= cc1; oacc[nt][1] *= cc1;
                oacc[nt][2] *= cc2; oacc[nt][3] *= cc2;
            }
            m1 = nm1; m2 = nm2;
            float rs1 = 0.f, rs2 = 0.f;
#pragma unroll
            for (int nt = 0; nt < 8; nt++) {
                sacc[nt][0] = __expf(sacc[nt][0] - nm1); rs1 += sacc[nt][0];
                sacc[nt][1] = __expf(sacc[nt][1] - nm1); rs1 += sacc[nt][1];
                sacc[nt][2] = __expf(sacc[nt][2] - nm2); rs2 += sacc[nt][2];
                sacc[nt][3] = __expf(sacc[nt][3] - nm2); rs2 += sacc[nt][3];
            }
            rs1 += __shfl_xor_sync(0xffffffffu, rs1, 1);
            rs1 += __shfl_xor_sync(0xffffffffu, rs1, 2);
            rs2 += __shfl_xor_sync(0xffffffffu, rs2, 1);
            rs2 += __shfl_xor_sync(0xffffffffu, rs2, 2);
            l1 += rs1; l2 += rs2;
            uint32_t pa[4][4], pl[4][4];
#pragma unroll
            for (int kp = 0; kp < 4; kp++) {
                int n0 = 2 * kp, n1 = 2 * kp + 1;
#define PPACK(dsti, x0, x1) { \
                float a0 = (x0), a1 = (x1); \
                __nv_bfloat16 b0 = __float2bfloat16(a0), b1 = __float2bfloat16(a1); \
                pa[kp][dsti] = ((uint32_t)*(uint16_t*)&b0) | ((uint32_t)*(uint16_t*)&b1 << 16); \
                float r0 = a0 - __bfloat162float(b0), r1f = a1 - __bfloat162float(b1); \
                __nv_bfloat16 c0b = __float2bfloat16(r0), c1b = __float2bfloat16(r1f); \
                pl[kp][dsti] = ((uint32_t)*(uint16_t*)&c0b) | ((uint32_t)*(uint16_t*)&c1b << 16); }
                PPACK(0, sacc[n0][0], sacc[n0][1]);
                PPACK(1, sacc[n0][2], sacc[n0][3]);
                PPACK(2, sacc[n1][0], sacc[n1][1]);
                PPACK(3, sacc[n1][2], sacc[n1][3]);
#undef PPACK
            }
#pragma unroll
            for (int kp = 0; kp < 4; kp++) {
                const uint32_t kc = kp * 16 + fcolo;
#pragma unroll
                for (int p = 0; p < 4; p++) {
                    uint32_t boff = (uint32_t)((p * 16 + frow) * RP + kc) * 2u;
                    uint32_t vh2[2][2], vl2[2][2];
                    LDSM4(vh2[0][0], vh2[0][1], vh2[1][0], vh2[1][1], vbase_h + boff);
                    LDSM4(vl2[0][0], vl2[0][1], vl2[1][0], vl2[1][1], vbase_l + boff);
#pragma unroll
                    for (int q = 0; q < 2; q++) {
                        MMA16816(oacc[2 * p + q], pa[kp], vh2[q]);
                        MMA16816(oacc[2 * p + q], pa[kp], vl2[q]);
                        MMA16816(oacc[2 * p + q], pl[kp], vh2[q]);
                    }
                }
            }
        }
    }

    float inv1 = 1.f / l1, inv2 = 1.f / l2;
    int row1 = b * S_ + q0 + r1;
    int row2 = row1 + 8;
#pragma unroll
    for (int nt = 0; nt < 8; nt++) {
        int col = h * HD_ + nt * 8 + c0;
        {
            float v0 = oacc[nt][0] * inv1, v1 = oacc[nt][1] * inv1;
            __nv_bfloat16 h0, l0, h1v, l1v;
            split_bf(v0, h0, l0); split_bf(v1, h1v, l1v);
            *(uint32_t*)(g_athi + (size_t)row1 * D_ + col) = pack2(h0, h1v);
            *(uint32_t*)(g_atlo + (size_t)row1 * D_ + col) = pack2(l0, l1v);
        }
        {
            float v0 = oacc[nt][2] * inv2, v1 = oacc[nt][3] * inv2;
            __nv_bfloat16 h0, l0, h1v, l1v;
            split_bf(v0, h0, l0); split_bf(v1, h1v, l1v);
            *(uint32_t*)(g_athi + (size_t)row2 * D_ + col) = pack2(h0, h1v);
            *(uint32_t*)(g_atlo + (size_t)row2 * D_ + col) = pack2(l0, l1v);
        }
    }
}

// ---------------- exact top-k (z -> sigmoid, monotonic) ----------------
__global__ __launch_bounds__(512) void topk_k() {
    int b = blockIdx.x;
    __shared__ float p[S_];
    for (int i = threadIdx.x; i < S_; i += 512) {
        float z = g_probs[b * S_ + i];
        p[i] = 1.f / (1.f + __expf(-z));
    }
    __syncthreads();
    int idx[4]; float v[4]; int cnt[4];
#pragma unroll
    for (int t = 0; t < 4; t++) {
        idx[t] = threadIdx.x + t * 512;
        v[t] = p[idx[t]];
        cnt[t] = 0;
    }
    for (int j = 0; j < S_; j++) {
        float pj = p[j];
#pragma unroll
        for (int t = 0; t < 4; t++)
            cnt[t] += (pj > v[t]) || (pj == v[t] && j < idx[t]) ? 1 : 0;
    }
#pragma unroll
    for (int t = 0; t < 4; t++) {
        if (cnt[t] < KSEL) {
            g_selidx[b * KSEL + cnt[t]] = idx[t];
            g_selprob[b * KSEL + cnt[t]] = v[t];
        }
    }
}

// ---------------- host launch ----------------
extern "C" void kernel_launch(void* const* d_in, const int* in_sizes, int n_in,
                              void* d_out, int out_size) {
    const int* ids            = (const int*)d_in[0];
    const int* iter           = (const int*)d_in[1];
    const float* emb          = (const float*)d_in[2];
    const float* iter_emb     = (const float*)d_in[3];
    const float* attn_norm_w  = (const float*)d_in[4];
    const float* Wqkv         = (const float*)d_in[5];
    const float* wo_w         = (const float*)d_in[6];
    const float* router_w     = (const float*)d_in[7];
    const float* mlp_norm_w   = (const float*)d_in[8];
    const float* gate_w       = (const float*)d_in[9];
    const float* up_w         = (const float*)d_in[10];
    const float* down_w       = (const float*)d_in[11];
    const float* final_norm_w = (const float*)d_in[12];
    float* out = (float*)d_out;

    float *px, *pselprob;
    int* pselidx;
    __nv_bfloat16 *pwhi, *pwlo, *phhi, *phlo, *pathi, *patlo, *phshi, *phslo, *pacthi, *pactlo;
    cudaGetSymbolAddress((void**)&px, g_x);
    cudaGetSymbolAddress((void**)&pselidx, g_selidx);
    cudaGetSymbolAddress((void**)&pselprob, g_selprob);
    cudaGetSymbolAddress((void**)&pwhi, g_whi);
    cudaGetSymbolAddress((void**)&pwlo, g_wlo);
    cudaGetSymbolAddress((void**)&phhi, g_hhi);
    cudaGetSymbolAddress((void**)&phlo, g_hlo);
    cudaGetSymbolAddress((void**)&pathi, g_athi);
    cudaGetSymbolAddress((void**)&patlo, g_atlo);
    cudaGetSymbolAddress((void**)&phshi, g_hshi);
    cudaGetSymbolAddress((void**)&phslo, g_hslo);
    cudaGetSymbolAddress((void**)&pacthi, g_acthi);
    cudaGetSymbolAddress((void**)&pactlo, g_actlo);

    constexpr int SMEM_G2 = 2 * (2 * 128 * 40 + 2 * 128 * 40) * 2;  // 81920 B (WN=2, 2 stages)
    constexpr int SMEM_G1 = 3 * (2 * 128 * 40 + 2 * 64 * 40) * 2;   // 92160 B (WN=1, 3 stages)
    constexpr int SMEM_ATTN = 3 * 4 * 64 * 72 * 2;                  // 110592 B (3 stages)
    cudaFuncSetAttribute(hgemm3_k<2>, cudaFuncAttributeMaxDynamicSharedMemorySize, SMEM_G2);
    cudaFuncSetAttribute(hgemm3_k<1>, cudaFuncAttributeMaxDynamicSharedMemorySize, SMEM_G1);
    cudaFuncSetAttribute(attn_tc_k, cudaFuncAttributeMaxDynamicSharedMemorySize, SMEM_ATTN);

    ropetab_k<<<S_, 32>>>();
    embed_k<<<T_, D_>>>(ids, iter, emb, iter_emb);
    cvt_all_k<<<(int)((WTOT + 255) / 256), 256>>>(Wqkv, wo_w, gate_w, up_w, down_w);

    const int MT  = T_ / 128;                 // 128
    const int MTS = (MS_ + 127) / 128;        // 103

    for (int l = 0; l < NL_; l++) {
        size_t lo = (size_t)l * LW;

        rmsnorm_bf_k<<<T_ / 4, 128>>>(px, attn_norm_w + l * D_, phhi, phlo, T_);
        // qkv GEMM with fused rope/split/pack epilogue (WN=2: good A reuse)
        {
            dim3 g((3 * D_ + 127) / 128, MT);
            hgemm3_k<2><<<g, 256, SMEM_G2>>>(phhi, phlo, pwhi + lo + WOFF_QKV, pwlo + lo + WOFF_QKV,
                                             nullptr, T_, 3 * D_, D_, 3, nullptr, nullptr, nullptr,
                                             nullptr);
        }
        {
            dim3 g(B_ * NH_, S_ / 128);
            attn_tc_k<<<g, 256, SMEM_ATTN>>>();
        }
        // x += attn @ wo^T, fused router partial-dot (WN=1)
        {
            dim3 g((D_ + 63) / 64, MT);
            hgemm3_k<1><<<g, 256, SMEM_G1>>>(pathi, patlo, pwhi + lo + WOFF_WO, pwlo + lo + WOFF_WO,
                                             px, T_, D_, D_, 1, nullptr, nullptr, nullptr,
                                             router_w + l * D_);
        }
        topk_k<<<B_, 512>>>();
        gather_rmsnorm_k<<<(MS_ + 3) / 4, 128>>>(px, mlp_norm_w + l * D_, phshi, phslo);
        // fused gate+up GEMM (interleaved N=1728) with silu*up epilogue (WN=2)
        {
            dim3 g((2 * FF_ + 127) / 128, MTS);
            hgemm3_k<2><<<g, 256, SMEM_G2>>>(phshi, phslo, pwhi + lo + WOFF_GU, pwlo + lo + WOFF_GU,
                                             nullptr, MS_, 2 * FF_, D_, 4, nullptr, nullptr, nullptr,
                                             nullptr);
        }
        // x[sel] += (act @ down^T) * prob (WN=1)
        {
            dim3 g((D_ + 63) / 64, MTS);
            hgemm3_k<1><<<g, 256, SMEM_G1>>>(pacthi, pactlo, pwhi + lo + WOFF_D, pwlo + lo + WOFF_D,
                                             nullptr, MS_, D_, FF_, 2, pselidx, pselprob, px,
                                             nullptr);
        }
    }

    rmsnorm_k<<<T_ / 4, 128>>>(px, final_norm_w, out, T_);
}

// round 15
// speedup vs baseline: 1.0312x; 1.0199x over previous
#include <cuda_runtime.h>
#include <cuda_bf16.h>
#include <math.h>
#include <stdint.h>

// ---------------- constants ----------------
constexpr int B_ = 8, S_ = 2048, D_ = 320, NH_ = 5, HD_ = 64, FF_ = 864, NL_ = 6, NLOOPS_ = 8;
constexpr int KSEL = 1638;
constexpr int T_ = B_ * S_;
constexpr int MS_ = B_ * KSEL;

constexpr size_t WOFF_QKV = 0;
constexpr size_t WOFF_WO  = 307200;
constexpr size_t WOFF_GU  = 409600;   // interleaved gate/up rows, 2*FF x D
constexpr size_t WOFF_D   = 962560;
constexpr size_t LW       = 1239040;
constexpr size_t WTOT     = LW * NL_;

// ---------------- scratch ----------------
__device__ float g_x[T_ * D_];
__device__ float g_probs[T_];
__device__ int   g_selidx[MS_];
__device__ float g_selprob[MS_];
__device__ float g_cos[S_ * 32];
__device__ float g_sin[S_ * 32];

__device__ __nv_bfloat16 g_whi[WTOT],       g_wlo[WTOT];
__device__ __nv_bfloat16 g_hhi[T_ * D_],    g_hlo[T_ * D_];
__device__ __nv_bfloat16 g_athi[T_ * D_],   g_atlo[T_ * D_];
__device__ __nv_bfloat16 g_hshi[MS_ * D_],  g_hslo[MS_ * D_];
__device__ __nv_bfloat16 g_acthi[MS_ * FF_],g_actlo[MS_ * FF_];

// attention operand buffers (head-major): [B*NH][S][HD]
__device__ __nv_bfloat16 g_qh[T_ * D_], g_ql[T_ * D_];
__device__ __nv_bfloat16 g_kh[T_ * D_], g_kl[T_ * D_];
__device__ __nv_bfloat16 g_vth[T_ * D_], g_vtl[T_ * D_];   // [bh][d][S]

__device__ __forceinline__ void split_bf(float f, __nv_bfloat16& h, __nv_bfloat16& l) {
    h = __float2bfloat16(f);
    l = __float2bfloat16(f - __bfloat162float(h));
}
__device__ __forceinline__ uint32_t pack2(__nv_bfloat16 a, __nv_bfloat16 b) {
    return ((uint32_t)*(uint16_t*)&a) | ((uint32_t)*(uint16_t*)&b << 16);
}

#define LDSM4(R0, R1, R2, R3, ADDR) \
    asm volatile("ldmatrix.sync.aligned.m8n8.x4.shared.b16 {%0,%1,%2,%3}, [%4];" \
                 : "=r"(R0), "=r"(R1), "=r"(R2), "=r"(R3) : "r"(ADDR))

#define MMA16816(d, a, b) asm volatile( \
    "mma.sync.aligned.m16n8k16.row.col.f32.bf16.bf16.f32 " \
    "{%0,%1,%2,%3},{%4,%5,%6,%7},{%8,%9},{%0,%1,%2,%3};\n" \
    : "+f"(d[0]), "+f"(d[1]), "+f"(d[2]), "+f"(d[3]) \
    : "r"(a[0]), "r"(a[1]), "r"(a[2]), "r"(a[3]), "r"(b[0]), "r"(b[1]))

// ---------------- rope tables ----------------
__global__ void ropetab_k() {
    int s = blockIdx.x, i = threadIdx.x;
    double freq = exp(-(double)i * (log(10000.0) / 32.0));
    double a = (double)s * freq;
    g_cos[s * 32 + i] = (float)cos(a);
    g_sin[s * 32 + i] = (float)sin(a);
}

// ---------------- embedding ----------------
__global__ void embed_k(const int* __restrict__ ids, const int* __restrict__ iter,
                        const float* __restrict__ emb, const float* __restrict__ iter_emb) {
    int t = blockIdx.x, d = threadIdx.x;
    int id = ids[t];
    float v = emb[(size_t)id * D_ + d];
    int it = iter[0];
    if (it < NLOOPS_) v += iter_emb[it * D_ + d];
    g_x[(size_t)t * D_ + d] = v;
}

// ---------------- weight conversion (gate/up interleaved) ----------------
__global__ void cvt_all_k(const float* __restrict__ Wqkv, const float* __restrict__ wo,
                          const float* __restrict__ gate, const float* __restrict__ up,
                          const float* __restrict__ down) {
    size_t i = (size_t)blockIdx.x * 256 + threadIdx.x;
    if (i >= WTOT) return;
    size_t l = i / LW, off = i % LW;
    const float* src; size_t so;
    if (off < WOFF_WO)      { src = Wqkv; so = l * 307200 + off; }
    else if (off < WOFF_GU) { src = wo;   so = l * 102400 + (off - WOFF_WO); }
    else if (off < WOFF_D)  {
        size_t idx = off - WOFF_GU;
        size_t row = idx / D_, col = idx % D_;
        size_t ff = row >> 1;
        src = (row & 1) ? up : gate;
        so = l * 276480 + ff * D_ + col;
    }
    else                    { src = down; so = l * 276480 + (off - WOFF_D); }
    float f = src[so];
    __nv_bfloat16 h, lo; split_bf(f, h, lo);
    g_whi[i] = h; g_wlo[i] = lo;
}

// ---------------- rmsnorm variants ----------------
__global__ void rmsnorm_k(const float* __restrict__ in, const float* __restrict__ w,
                          float* __restrict__ out, int nrows) {
    int warp = (blockIdx.x * blockDim.x + threadIdx.x) >> 5;
    int lane = threadIdx.x & 31;
    if (warp >= nrows) return;
    const float* r = in + (size_t)warp * D_;
    float e[10]; float ss = 0.f;
#pragma unroll
    for (int i = 0; i < 10; i++) { e[i] = r[lane + 32 * i]; ss += e[i] * e[i]; }
#pragma unroll
    for (int o = 16; o > 0; o >>= 1) ss += __shfl_xor_sync(0xffffffffu, ss, o);
    float rr = rsqrtf(ss * (1.0f / D_) + 1e-6f);
    float* po = out + (size_t)warp * D_;
#pragma unroll
    for (int i = 0; i < 10; i++) po[lane + 32 * i] = e[i] * rr * w[lane + 32 * i];
}

// also zeroes g_probs[row] for the fused-router atomic accumulation
__global__ void rmsnorm_bf_k(const float* __restrict__ in, const float* __restrict__ w,
                             __nv_bfloat16* __restrict__ ohi, __nv_bfloat16* __restrict__ olo,
                             int nrows) {
    int warp = (blockIdx.x * blockDim.x + threadIdx.x) >> 5;
    int lane = threadIdx.x & 31;
    if (warp >= nrows) return;
    if (lane == 0) g_probs[warp] = 0.f;
    const float* r = in + (size_t)warp * D_;
    float e[10]; float ss = 0.f;
#pragma unroll
    for (int i = 0; i < 10; i++) { e[i] = r[lane + 32 * i]; ss += e[i] * e[i]; }
#pragma unroll
    for (int o = 16; o > 0; o >>= 1) ss += __shfl_xor_sync(0xffffffffu, ss, o);
    float rr = rsqrtf(ss * (1.0f / D_) + 1e-6f);
#pragma unroll
    for (int i = 0; i < 10; i++) {
        float v = e[i] * rr * w[lane + 32 * i];
        __nv_bfloat16 h, l; split_bf(v, h, l);
        ohi[(size_t)warp * D_ + lane + 32 * i] = h;
        olo[(size_t)warp * D_ + lane + 32 * i] = l;
    }
}

__global__ void gather_rmsnorm_k(const float* __restrict__ in, const float* __restrict__ w,
                                 __nv_bfloat16* __restrict__ ohi, __nv_bfloat16* __restrict__ olo) {
    int warp = (blockIdx.x * blockDim.x + threadIdx.x) >> 5;
    int lane = threadIdx.x & 31;
    if (warp >= MS_) return;
    int b = warp / KSEL;
    int tok = g_selidx[warp];
    const float* r = in + (size_t)(b * S_ + tok) * D_;
    float e[10]; float ss = 0.f;
#pragma unroll
    for (int i = 0; i < 10; i++) { e[i] = r[lane + 32 * i]; ss += e[i] * e[i]; }
#pragma unroll
    for (int o = 16; o > 0; o >>= 1) ss += __shfl_xor_sync(0xffffffffu, ss, o);
    float rr = rsqrtf(ss * (1.0f / D_) + 1e-6f);
#pragma unroll
    for (int i = 0; i < 10; i++) {
        float v = e[i] * rr * w[lane + 32 * i];
        __nv_bfloat16 h, l; split_bf(v, h, l);
        ohi[(size_t)warp * D_ + lane + 32 * i] = h;
        olo[(size_t)warp * D_ + lane + 32 * i] = l;
    }
}

// =====================================================================
// bf16x3 tensor-core GEMM, templated on WN: BN = 64*WN.
// WN=2: 2-stage, occupancy 2. WN=1: 2-stage, occupancy 3 (wave-tail killer).
// epi: 0 store, 1 += C (+ fused router partial-dot if rw), 2 scatter-add,
//      3 fused qkv rope/scale/split/pack, 4 fused gate/up silu
// =====================================================================
template <int WN>
__global__ __launch_bounds__(256, (WN == 1) ? 3 : 2) void hgemm3_k(
    const __nv_bfloat16* __restrict__ Ahi, const __nv_bfloat16* __restrict__ Alo,
    const __nv_bfloat16* __restrict__ Bhi, const __nv_bfloat16* __restrict__ Blo,
    float* __restrict__ C, int M, int N, int K, int epi,
    const int* __restrict__ selidx, const float* __restrict__ selprob,
    float* __restrict__ xout, const float* __restrict__ rw) {
    extern __shared__ __nv_bfloat16 sm[];
    constexpr int BN  = 64 * WN;
    constexpr int MT  = WN;
    constexpr int ASZ = 128 * 40;
    constexpr int BSZ = BN * 40;
    constexpr int STG = 2 * ASZ + 2 * BSZ;

    const int tid = threadIdx.x;
    const int lane = tid & 31, warp = tid >> 5;
    const int wn = warp & (WN - 1);
    const int wm = warp / WN;
    const int bm = blockIdx.y * 128, bn = blockIdx.x * BN;

    float acc[MT][8][4];
#pragma unroll
    for (int a = 0; a < MT; a++)
#pragma unroll
        for (int b = 0; b < 8; b++)
#pragma unroll
            for (int c = 0; c < 4; c++) acc[a][b][c] = 0.f;

    uint32_t smemBase = (uint32_t)__cvta_generic_to_shared(sm);
    const int KT = K / 32;
    const int crow = tid >> 2, cseg = tid & 3;

    auto load_stage = [&](int kt, int s) {
        int k0 = kt * 32;
#pragma unroll
        for (int arr = 0; arr < 4; arr++) {
            const __nv_bfloat16* src = arr == 0 ? Ahi : arr == 1 ? Alo : arr == 2 ? Bhi : Blo;
            const bool isA = arr < 2;
            const int lim = isA ? M : N;
            const int gbase = isA ? bm : bn;
            const int nIter = isA ? 2 : BN / 64;
            const uint32_t abase = (arr < 2) ? (uint32_t)(arr * ASZ)
                                             : (uint32_t)(2 * ASZ + (arr - 2) * BSZ);
#pragma unroll
            for (int i = 0; i < 2; i++) {
                if (i >= nIter) break;
                int row = crow + i * 64;
                int g = gbase + row;
                const __nv_bfloat16* gp = src + (size_t)g * K + k0 + cseg * 8;
                uint32_t dst = smemBase + (uint32_t)(s * STG + abase + row * 40 + cseg * 8) * 2u;
                int sz = (g < lim) ? 16 : 0;
                asm volatile("cp.async.cg.shared.global [%0], [%1], 16, %2;\n"
                             :: "r"(dst), "l"(gp), "r"(sz));
            }
        }
        asm volatile("cp.async.commit_group;\n");
    };

    const uint32_t arow = ((lane >> 3) & 1) * 8 + (lane & 7);
    const uint32_t acolo = (lane >> 4) * 8;
    const uint32_t brow = (lane >> 4) * 8 + (lane & 7);
    const uint32_t bcolo = ((lane >> 3) & 1) * 8;

    auto compute = [&](int s) {
        const uint32_t base = smemBase + (uint32_t)(s * STG) * 2u;
#pragma unroll
        for (int kk = 0; kk < 2; kk++) {
            const uint32_t k0 = kk * 16;
            uint32_t ah[MT][4], al[MT][4];
#pragma unroll
            for (int mt = 0; mt < MT; mt++) {
                uint32_t aoff = (uint32_t)((wm * 16 * MT + mt * 16 + arow) * 40 + k0 + acolo) * 2u;
                LDSM4(ah[mt][0], ah[mt][1], ah[mt][2], ah[mt][3], base + aoff);
                LDSM4(al[mt][0], al[mt][1], al[mt][2], al[mt][3], base + ASZ * 2u + aoff);
            }
#pragma unroll
            for (int p = 0; p < 4; p++) {
                uint32_t boff = (uint32_t)((wn * 64 + p * 16 + brow) * 40 + k0 + bcolo) * 2u;
                uint32_t bhf[2][2], blf[2][2];
                LDSM4(bhf[0][0], bhf[0][1], bhf[1][0], bhf[1][1], base + 2u * ASZ * 2u + boff);
                LDSM4(blf[0][0], blf[0][1], blf[1][0], blf[1][1],
                      base + (2u * ASZ + BSZ) * 2u + boff);
#pragma unroll
                for (int q = 0; q < 2; q++) {
                    const int nt = 2 * p + q;
#pragma unroll
                    for (int mt = 0; mt < MT; mt++) {
                        MMA16816(acc[mt][nt], ah[mt], bhf[q]);
                        MMA16816(acc[mt][nt], ah[mt], blf[q]);
                        MMA16816(acc[mt][nt], al[mt], bhf[q]);
                    }
                }
            }
        }
    };

    load_stage(0, 0);
    if (KT > 1) load_stage(1, 1);
    for (int kt = 0; kt < KT; kt++) {
        const int s = kt & 1;
        if (kt + 1 < KT) asm volatile("cp.async.wait_group 1;\n");
        else             asm volatile("cp.async.wait_group 0;\n");
        __syncthreads();
        compute(s);
        __syncthreads();
        if (kt + 2 < KT) load_stage(kt + 2, s);
    }

    // ---------------- epilogues ----------------
    if (epi == 3) {
        int nb = (bn + wn * 64) >> 6;
        if (nb < 15) {
            int region = nb / 5, hd = nb % 5;
#pragma unroll
            for (int mt = 0; mt < MT; mt++) {
#pragma unroll
                for (int ci = 0; ci < 2; ci++) {
                    int m = bm + wm * 16 * MT + mt * 16 + (lane >> 2) + ci * 8;
                    if (m >= M) continue;
                    int b = m / S_, s = m - b * S_;
                    size_t bh_ = (size_t)(b * NH_ + hd);
                    if (region < 2) {
                        // q gets pre-scaled by 1/sqrt(HD)=0.125 (exact power of 2)
                        const float qsc = region ? 1.f : 0.125f;
                        __nv_bfloat16* dh = (region ? g_kh : g_qh) + (bh_ * S_ + s) * HD_;
                        __nv_bfloat16* dl = (region ? g_kl : g_ql) + (bh_ * S_ + s) * HD_;
#pragma unroll
                        for (int nt = 0; nt < 4; nt++) {
                            int d0 = nt * 8 + (lane & 3) * 2;
                            float r1[2], r2[2];
#pragma unroll
                            for (int j = 0; j < 2; j++) {
                                int dd = d0 + j;
                                float v1 = acc[mt][nt][ci * 2 + j];
                                float v2 = acc[mt][nt + 4][ci * 2 + j];
                                float co = g_cos[s * 32 + dd];
                                float si = g_sin[s * 32 + dd];
                                r1[j] = (v1 * co - v2 * si) * qsc;
                                r2[j] = (v2 * co + v1 * si) * qsc;
                            }
                            __nv_bfloat16 h0, l0, h1, l1;
                            split_bf(r1[0], h0, l0); split_bf(r1[1], h1, l1);
                            *(uint32_t*)(dh + d0) = pack2(h0, h1);
                            *(uint32_t*)(dl + d0) = pack2(l0, l1);
                            split_bf(r2[0], h0, l0); split_bf(r2[1], h1, l1);
                            *(uint32_t*)(dh + d0 + 32) = pack2(h0, h1);
                            *(uint32_t*)(dl + d0 + 32) = pack2(l0, l1);
                        }
                    } else {
#pragma unroll
                        for (int nt = 0; nt < 8; nt++) {
#pragma unroll
                            for (int j = 0; j < 2; j++) {
                                int d = nt * 8 + (lane & 3) * 2 + j;
                                float v = acc[mt][nt][ci * 2 + j];
                                __nv_bfloat16 hh, ll; split_bf(v, hh, ll);
                                size_t idx = (bh_ * HD_ + d) * S_ + s;
                                g_vth[idx] = hh;
                                g_vtl[idx] = ll;
                            }
                        }
                    }
                }
            }
        }
    } else if (epi == 4) {
#pragma unroll
        for (int mt = 0; mt < MT; mt++) {
#pragma unroll
            for (int ci = 0; ci < 2; ci++) {
                int m = bm + wm * 16 * MT + mt * 16 + (lane >> 2) + ci * 8;
                if (m >= M) continue;
#pragma unroll
                for (int nt = 0; nt < 8; nt++) {
                    int n = bn + wn * 64 + nt * 8 + (lane & 3) * 2;
                    if (n + 1 < N) {
                        float gv = acc[mt][nt][ci * 2 + 0];
                        float uv = acc[mt][nt][ci * 2 + 1];
                        float v = gv / (1.f + __expf(-gv)) * uv;
                        int ff = n >> 1;
                        __nv_bfloat16 h, l; split_bf(v, h, l);
                        g_acthi[(size_t)m * FF_ + ff] = h;
                        g_actlo[(size_t)m * FF_ + ff] = l;
                    }
                }
            }
        }
    } else {
#pragma unroll
        for (int mt = 0; mt < MT; mt++) {
#pragma unroll
            for (int ci = 0; ci < 2; ci++) {
                int m = bm + wm * 16 * MT + mt * 16 + (lane >> 2) + ci * 8;
                if (m >= M) continue;
                int xrow = 0; float sc = 0.f;
                if (epi == 2) { xrow = (m / KSEL) * S_ + selidx[m]; sc = selprob[m]; }
                float zp = 0.f;
#pragma unroll
                for (int nt = 0; nt < 8; nt++) {
                    int n = bn + wn * 64 + nt * 8 + (lane & 3) * 2;
                    float v0 = acc[mt][nt][ci * 2 + 0];
                    float v1 = acc[mt][nt][ci * 2 + 1];
                    if (n + 1 < N) {
                        if (epi == 0) {
                            *(float2*)(C + (size_t)m * N + n) = make_float2(v0, v1);
                        } else if (epi == 1) {
                            float2 c = *(float2*)(C + (size_t)m * N + n);
                            c.x += v0; c.y += v1;
                            *(float2*)(C + (size_t)m * N + n) = c;
                            if (rw) {
                                float2 w2 = *(const float2*)(rw + n);
                                zp += c.x * w2.x + c.y * w2.y;
                            }
                        } else {
                            float2 c = *(float2*)(xout + (size_t)xrow * D_ + n);
                            c.x += v0 * sc; c.y += v1 * sc;
                            *(float2*)(xout + (size_t)xrow * D_ + n) = c;
                        }
                    } else if (n < N) {
                        if (epi == 0) C[(size_t)m * N + n] = v0;
                        else if (epi == 1) C[(size_t)m * N + n] += v0;
                        else xout[(size_t)xrow * D_ + n] += v0 * sc;
                    }
                }
                if (epi == 1 && rw) {
                    zp += __shfl_xor_sync(0xffffffffu, zp, 1);
                    zp += __shfl_xor_sync(0xffffffffu, zp, 2);
                    if ((lane & 3) == 0) atomicAdd(&g_probs[m], zp);
                }
            }
        }
    }
}

// =====================================================================
// tensor-core flash attention: 256 threads, 128-row qtiles, heavy-first,
// 3-stage cp.async with ONE __syncthreads per tile. q pre-scaled.
// =====================================================================
__global__ __launch_bounds__(256, 1) void attn_tc_k() {
    extern __shared__ __nv_bfloat16 asm_[];
    constexpr int RP = 72;
    constexpr int TSZ = 64 * RP;
    constexpr int STG = 4 * TSZ;

    const int bh = blockIdx.x;
    const int qtile = (S_ / 128 - 1) - blockIdx.y;   // heavy tiles first
    const int b = bh / NH_, h = bh % NH_;
    const int tid = threadIdx.x, lane = tid & 31, warp = tid >> 5;
    const int q0 = qtile * 128 + warp * 16;
    const int r1 = lane >> 2, c0 = (lane & 3) * 2;

    uint32_t qh[4][4], ql[4][4];
    {
        const __nv_bfloat16* Qh = g_qh + ((size_t)bh * S_ + q0) * HD_;
        const __nv_bfloat16* Ql = g_ql + ((size_t)bh * S_ + q0) * HD_;
#pragma unroll
        for (int ks = 0; ks < 4; ks++) {
            int kc = ks * 16 + c0;
            qh[ks][0] = *(const uint32_t*)(Qh + r1 * 64 + kc);
            qh[ks][1] = *(const uint32_t*)(Qh + (r1 + 8) * 64 + kc);
            qh[ks][2] = *(const uint32_t*)(Qh + r1 * 64 + kc + 8);
            qh[ks][3] = *(const uint32_t*)(Qh + (r1 + 8) * 64 + kc + 8);
            ql[ks][0] = *(const uint32_t*)(Ql + r1 * 64 + kc);
            ql[ks][1] = *(const uint32_t*)(Ql + (r1 + 8) * 64 + kc);
            ql[ks][2] = *(const uint32_t*)(Ql + r1 * 64 + kc + 8);
            ql[ks][3] = *(const uint32_t*)(Ql + (r1 + 8) * 64 + kc + 8);
        }
    }

    float oacc[8][4];
#pragma unroll
    for (int i = 0; i < 8; i++)
#pragma unroll
        for (int j = 0; j < 4; j++) oacc[i][j] = 0.f;
    float m1 = -1e30f, m2 = -1e30f, l1 = 0.f, l2 = 0.f;

    uint32_t smemBase = (uint32_t)__cvta_generic_to_shared(asm_);
    const int NT = 2 * qtile + 2;
    const int lrow = tid >> 2, lch = tid & 3;
    const uint32_t frow = (lane >> 4) * 8 + (lane & 7);
    const uint32_t fcolo = ((lane >> 3) & 1) * 8;

    auto load_tile = [&](int kt, int st) {
        int k0 = kt * 64;
        const __nv_bfloat16* srcs[4] = {
            g_kh + ((size_t)bh * S_ + k0) * HD_,
            g_kl + ((size_t)bh * S_ + k0) * HD_,
            g_vth + (size_t)bh * HD_ * S_ + k0,
            g_vtl + (size_t)bh * HD_ * S_ + k0};
        const size_t rstride[4] = {HD_, HD_, S_, S_};
#pragma unroll
        for (int arr = 0; arr < 4; arr++) {
#pragma unroll
            for (int i = 0; i < 2; i++) {
                int ch = lch + i * 4;
                const __nv_bfloat16* gp = srcs[arr] + (size_t)lrow * rstride[arr] + ch * 8;
                uint32_t dst = smemBase + (uint32_t)(st * STG + arr * TSZ + lrow * RP + ch * 8) * 2u;
                asm volatile("cp.async.cg.shared.global [%0], [%1], 16;\n" :: "r"(dst), "l"(gp));
            }
        }
        asm volatile("cp.async.commit_group;\n");
    };

    load_tile(0, 0);
    if (NT > 1) load_tile(1, 1);
    for (int kt = 0; kt < NT; kt++) {
        if (kt + 1 < NT) asm volatile("cp.async.wait_group 1;\n");
        else             asm volatile("cp.async.wait_group 0;\n");
        __syncthreads();
        if (kt + 2 < NT) load_tile(kt + 2, (kt + 2) % 3);
        const int k0 = kt * 64;
        if (k0 <= q0 + 15) {
            const int st = kt % 3;
            const uint32_t kbase_h = smemBase + (uint32_t)(st * STG) * 2u;
            const uint32_t kbase_l = kbase_h + (uint32_t)TSZ * 2u;
            const uint32_t vbase_h = kbase_h + 2u * (uint32_t)TSZ * 2u;
            const uint32_t vbase_l = kbase_h + 3u * (uint32_t)TSZ * 2u;

            float sacc[8][4];
#pragma unroll
            for (int i = 0; i < 8; i++)
#pragma unroll
                for (int j = 0; j < 4; j++) sacc[i][j] = 0.f;

#pragma unroll
            for (int ks = 0; ks < 4; ks++) {
                const uint32_t kc = ks * 16 + fcolo;
#pragma unroll
                for (int p = 0; p < 4; p++) {
                    uint32_t boff = (uint32_t)((p * 16 + frow) * RP + kc) * 2u;
                    uint32_t kh2[2][2], kl2[2][2];
                    LDSM4(kh2[0][0], kh2[0][1], kh2[1][0], kh2[1][1], kbase_h + boff);
                    LDSM4(kl2[0][0], kl2[0][1], kl2[1][0], kl2[1][1], kbase_l + boff);
#pragma unroll
                    for (int q = 0; q < 2; q++) {
                        MMA16816(sacc[2 * p + q], qh[ks], kh2[q]);
                        MMA16816(sacc[2 * p + q], qh[ks], kl2[q]);
                        MMA16816(sacc[2 * p + q], ql[ks], kh2[q]);
                    }
                }
            }
            const bool diag = (k0 + 63 > q0);
            if (diag) {
#pragma unroll
                for (int nt = 0; nt < 8; nt++) {
#pragma unroll
                    for (int j = 0; j < 4; j++) {
                        int col = k0 + nt * 8 + c0 + (j & 1);
                        int row = q0 + r1 + ((j >= 2) ? 8 : 0);
                        if (col > row) sacc[nt][j] = -1e30f;
                    }
                }
            }
            float t1 = -1e30f, t2 = -1e30f;
#pragma unroll
            for (int nt = 0; nt < 8; nt++) {
                t1 = fmaxf(t1, fmaxf(sacc[nt][0], sacc[nt][1]));
                t2 = fmaxf(t2, fmaxf(sacc[nt][2], sacc[nt][3]));
            }
            t1 = fmaxf(t1, __shfl_xor_sync(0xffffffffu, t1, 1));
            t1 = fmaxf(t1, __shfl_xor_sync(0xffffffffu, t1, 2));
            t2 = fmaxf(t2, __shfl_xor_sync(0xffffffffu, t2, 1));
            t2 = fmaxf(t2, __shfl_xor_sync(0xffffffffu, t2, 2));
            float nm1 = fmaxf(m1, t1), nm2 = fmaxf(m2, t2);
            float cc1 = __expf(m1 - nm1), cc2 = __expf(m2 - nm2);
            l1 *= cc1; l2 *= cc2;
#pragma unroll
            for (int nt = 0; nt < 8; nt++) {
                oacc[nt][0] *= cc1; oacc[nt][1] *= cc1;
                oacc[nt][2] *= cc2; oacc[nt][3] *= cc2;
            }
            m1 = nm1; m2 = nm2;
            float rs1 = 0.f, rs2 = 0.f;
#pragma unroll
            for (int nt = 0; nt < 8; nt++) {
                sacc[nt][0] = __expf(sacc[nt][0] - nm1); rs1 += sacc[nt][0];
                sacc[nt][1] = __expf(sacc[nt][1] - nm1); rs1 += sacc[nt][1];
                sacc[nt][2] = __expf(sacc[nt][2] - nm2); rs2 += sacc[nt][2];
                sacc[nt][3] = __expf(sacc[nt][3] - nm2); rs2 += sacc[nt][3];
            }
            rs1 += __shfl_xor_sync(0xffffffffu, rs1, 1);
            rs1 += __shfl_xor_sync(0xffffffffu, rs1, 2);
            rs2 += __shfl_xor_sync(0xffffffffu, rs2, 1);
            rs2 += __shfl_xor_sync(0xffffffffu, rs2, 2);
            l1 += rs1; l2 += rs2;
            uint32_t pa[4][4], pl[4][4];
#pragma unroll
            for (int kp = 0; kp < 4; kp++) {
                int n0 = 2 * kp, n1 = 2 * kp + 1;
#define PPACK(dsti, x0, x1) { \
                float a0 = (x0), a1 = (x1); \
                __nv_bfloat16 b0 = __float2bfloat16(a0), b1 = __float2bfloat16(a1); \
                pa[kp][dsti] = ((uint32_t)*(uint16_t*)&b0) | ((uint32_t)*(uint16_t*)&b1 << 16); \
                float r0 = a0 - __bfloat162float(b0), r1f = a1 - __bfloat162float(b1); \
                __nv_bfloat16 c0b = __float2bfloat16(r0), c1b = __float2bfloat16(r1f); \
                pl[kp][dsti] = ((uint32_t)*(uint16_t*)&c0b) | ((uint32_t)*(uint16_t*)&c1b << 16); }
                PPACK(0, sacc[n0][0], sacc[n0][1]);
                PPACK(1, sacc[n0][2], sacc[n0][3]);
                PPACK(2, sacc[n1][0], sacc[n1][1]);
                PPACK(3, sacc[n1][2], sacc[n1][3]);
#undef PPACK
            }
#pragma unroll
            for (int kp = 0; kp < 4; kp++) {
                const uint32_t kc = kp * 16 + fcolo;
#pragma unroll
                for (int p = 0; p < 4; p++) {
                    uint32_t boff = (uint32_t)((p * 16 + frow) * RP + kc) * 2u;
                    uint32_t vh2[2][2], vl2[2][2];
                    LDSM4(vh2[0][0], vh2[0][1], vh2[1][0], vh2[1][1], vbase_h + boff);
                    LDSM4(vl2[0][0], vl2[0][1], vl2[1][0], vl2[1][1], vbase_l + boff);
#pragma unroll
                    for (int q = 0; q < 2; q++) {
                        MMA16816(oacc[2 * p + q], pa[kp], vh2[q]);
                        MMA16816(oacc[2 * p + q], pa[kp], vl2[q]);
                        MMA16816(oacc[2 * p + q], pl[kp], vh2[q]);
                    }
                }
            }
        }
    }

    float inv1 = 1.f / l1, inv2 = 1.f / l2;
    int row1 = b * S_ + q0 + r1;
    int row2 = row1 + 8;
#pragma unroll
    for (int nt = 0; nt < 8; nt++) {
        int col = h * HD_ + nt * 8 + c0;
        {
            float v0 = oacc[nt][0] * inv1, v1 = oacc[nt][1] * inv1;
            __nv_bfloat16 h0, l0, h1v, l1v;
            split_bf(v0, h0, l0); split_bf(v1, h1v, l1v);
            *(uint32_t*)(g_athi + (size_t)row1 * D_ + col) = pack2(h0, h1v);
            *(uint32_t*)(g_atlo + (size_t)row1 * D_ + col) = pack2(l0, l1v);
        }
        {
            float v0 = oacc[nt][2] * inv2, v1 = oacc[nt][3] * inv2;
            __nv_bfloat16 h0, l0, h1v, l1v;
            split_bf(v0, h0, l0); split_bf(v1, h1v, l1v);
            *(uint32_t*)(g_athi + (size_t)row2 * D_ + col) = pack2(h0, h1v);
            *(uint32_t*)(g_atlo + (size_t)row2 * D_ + col) = pack2(l0, l1v);
        }
    }
}

// ---------------- exact top-k (z -> sigmoid, monotonic) ----------------
__global__ __launch_bounds__(512) void topk_k() {
    int b = blockIdx.x;
    __shared__ float p[S_];
    for (int i = threadIdx.x; i < S_; i += 512) {
        float z = g_probs[b * S_ + i];
        p[i] = 1.f / (1.f + __expf(-z));
    }
    __syncthreads();
    int idx[4]; float v[4]; int cnt[4];
#pragma unroll
    for (int t = 0; t < 4; t++) {
        idx[t] = threadIdx.x + t * 512;
        v[t] = p[idx[t]];
        cnt[t] = 0;
    }
    for (int j = 0; j < S_; j++) {
        float pj = p[j];
#pragma unroll
        for (int t = 0; t < 4; t++)
            cnt[t] += (pj > v[t]) || (pj == v[t] && j < idx[t]) ? 1 : 0;
    }
#pragma unroll
    for (int t = 0; t < 4; t++) {
        if (cnt[t] < KSEL) {
            g_selidx[b * KSEL + cnt[t]] = idx[t];
            g_selprob[b * KSEL + cnt[t]] = v[t];
        }
    }
}

// ---------------- host launch ----------------
extern "C" void kernel_launch(void* const* d_in, const int* in_sizes, int n_in,
                              void* d_out, int out_size) {
    const int* ids            = (const int*)d_in[0];
    const int* iter           = (const int*)d_in[1];
    const float* emb          = (const float*)d_in[2];
    const float* iter_emb     = (const float*)d_in[3];
    const float* attn_norm_w  = (const float*)d_in[4];
    const float* Wqkv         = (const float*)d_in[5];
    const float* wo_w         = (const float*)d_in[6];
    const float* router_w     = (const float*)d_in[7];
    const float* mlp_norm_w   = (const float*)d_in[8];
    const float* gate_w       = (const float*)d_in[9];
    const float* up_w         = (const float*)d_in[10];
    const float* down_w       = (const float*)d_in[11];
    const float* final_norm_w = (const float*)d_in[12];
    float* out = (float*)d_out;

    float *px, *pselprob;
    int* pselidx;
    __nv_bfloat16 *pwhi, *pwlo, *phhi, *phlo, *pathi, *patlo, *phshi, *phslo, *pacthi, *pactlo;
    cudaGetSymbolAddress((void**)&px, g_x);
    cudaGetSymbolAddress((void**)&pselidx, g_selidx);
    cudaGetSymbolAddress((void**)&pselprob, g_selprob);
    cudaGetSymbolAddress((void**)&pwhi, g_whi);
    cudaGetSymbolAddress((void**)&pwlo, g_wlo);
    cudaGetSymbolAddress((void**)&phhi, g_hhi);
    cudaGetSymbolAddress((void**)&phlo, g_hlo);
    cudaGetSymbolAddress((void**)&pathi, g_athi);
    cudaGetSymbolAddress((void**)&patlo, g_atlo);
    cudaGetSymbolAddress((void**)&phshi, g_hshi);
    cudaGetSymbolAddress((void**)&phslo, g_hslo);
    cudaGetSymbolAddress((void**)&pacthi, g_acthi);
    cudaGetSymbolAddress((void**)&pactlo, g_actlo);

    constexpr int SMEM_G2 = 2 * (2 * 128 * 40 + 2 * 128 * 40) * 2;  // 81920 B (WN=2, occ 2)
    constexpr int SMEM_G1 = 2 * (2 * 128 * 40 + 2 * 64 * 40) * 2;   // 61440 B (WN=1, occ 3)
    constexpr int SMEM_ATTN = 3 * 4 * 64 * 72 * 2;                  // 110592 B (3 stages)
    cudaFuncSetAttribute(hgemm3_k<2>, cudaFuncAttributeMaxDynamicSharedMemorySize, SMEM_G2);
    cudaFuncSetAttribute(hgemm3_k<1>, cudaFuncAttributeMaxDynamicSharedMemorySize, SMEM_G1);
    cudaFuncSetAttribute(attn_tc_k, cudaFuncAttributeMaxDynamicSharedMemorySize, SMEM_ATTN);

    ropetab_k<<<S_, 32>>>();
    embed_k<<<T_, D_>>>(ids, iter, emb, iter_emb);
    cvt_all_k<<<(int)((WTOT + 255) / 256), 256>>>(Wqkv, wo_w, gate_w, up_w, down_w);

    const int MT  = T_ / 128;                 // 128
    const int MTS = (MS_ + 127) / 128;        // 103

    for (int l = 0; l < NL_; l++) {
        size_t lo = (size_t)l * LW;

        rmsnorm_bf_k<<<T_ / 4, 128>>>(px, attn_norm_w + l * D_, phhi, phlo, T_);
        // qkv GEMM with fused rope/scale/split/pack epilogue (WN=2)
        {
            dim3 g((3 * D_ + 127) / 128, MT);
            hgemm3_k<2><<<g, 256, SMEM_G2>>>(phhi, phlo, pwhi + lo + WOFF_QKV, pwlo + lo + WOFF_QKV,
                                             nullptr, T_, 3 * D_, D_, 3, nullptr, nullptr, nullptr,
                                             nullptr);
        }
        {
            dim3 g(B_ * NH_, S_ / 128);
            attn_tc_k<<<g, 256, SMEM_ATTN>>>();
        }
        // x += attn @ wo^T, fused router partial-dot (WN=1, occ 3)
        {
            dim3 g((D_ + 63) / 64, MT);
            hgemm3_k<1><<<g, 256, SMEM_G1>>>(pathi, patlo, pwhi + lo + WOFF_WO, pwlo + lo + WOFF_WO,
                                             px, T_, D_, D_, 1, nullptr, nullptr, nullptr,
                                             router_w + l * D_);
        }
        topk_k<<<B_, 512>>>();
        gather_rmsnorm_k<<<(MS_ + 3) / 4, 128>>>(px, mlp_norm_w + l * D_, phshi, phslo);
        // fused gate+up GEMM (interleaved N=1728) with silu*up epilogue (WN=2)
        {
            dim3 g((2 * FF_ + 127) / 128, MTS);
            hgemm3_k<2><<<g, 256, SMEM_G2>>>(phshi, phslo, pwhi + lo + WOFF_GU, pwlo + lo + WOFF_GU,
                                             nullptr, MS_, 2 * FF_, D_, 4, nullptr, nullptr, nullptr,
                                             nullptr);
        }
        // x[sel] += (act @ down^T) * prob (WN=1, occ 3)
        {
            dim3 g((D_ + 63) / 64, MTS);
            hgemm3_k<1><<<g, 256, SMEM_G1>>>(pacthi, pactlo, pwhi + lo + WOFF_D, pwlo + lo + WOFF_D,
                                             nullptr, MS_, D_, FF_, 2, pselidx, pselprob, px,
                                             nullptr);
        }
    }

    rmsnorm_k<<<T_ / 4, 128>>>(px, final_norm_w, out, T_);
}

// round 16
// speedup vs baseline: 1.1157x; 1.0820x over previous
#include <cuda_runtime.h>
#include <cuda_bf16.h>
#include <math.h>
#include <stdint.h>

// ---------------- constants ----------------
constexpr int B_ = 8, S_ = 2048, D_ = 320, NH_ = 5, HD_ = 64, FF_ = 864, NL_ = 6, NLOOPS_ = 8;
constexpr int KSEL = 1638;
constexpr int T_ = B_ * S_;
constexpr int MS_ = B_ * KSEL;

constexpr size_t WOFF_QKV = 0;
constexpr size_t WOFF_WO  = 307200;
constexpr size_t WOFF_GU  = 409600;   // interleaved gate/up rows, 2*FF x D
constexpr size_t WOFF_D   = 962560;
constexpr size_t LW       = 1239040;
constexpr size_t WTOT     = LW * NL_;

// ---------------- scratch ----------------
__device__ float g_x[T_ * D_];
__device__ float g_probs[T_];
__device__ int   g_selidx[MS_];
__device__ float g_selprob[MS_];
__device__ float g_cos[S_ * 32];
__device__ float g_sin[S_ * 32];

__device__ __nv_bfloat16 g_whi[WTOT],       g_wlo[WTOT];
__device__ __nv_bfloat16 g_hhi[T_ * D_],    g_hlo[T_ * D_];
__device__ __nv_bfloat16 g_athi[T_ * D_],   g_atlo[T_ * D_];
__device__ __nv_bfloat16 g_hshi[MS_ * D_],  g_hslo[MS_ * D_];
__device__ __nv_bfloat16 g_acthi[MS_ * FF_],g_actlo[MS_ * FF_];

// attention operand buffers (head-major): [B*NH][S][HD]
__device__ __nv_bfloat16 g_qh[T_ * D_], g_ql[T_ * D_];
__device__ __nv_bfloat16 g_kh[T_ * D_], g_kl[T_ * D_];
__device__ __nv_bfloat16 g_vth[T_ * D_], g_vtl[T_ * D_];   // [bh][d][S]

__device__ __forceinline__ void split_bf(float f, __nv_bfloat16& h, __nv_bfloat16& l) {
    h = __float2bfloat16(f);
    l = __float2bfloat16(f - __bfloat162float(h));
}
__device__ __forceinline__ uint32_t pack2(__nv_bfloat16 a, __nv_bfloat16 b) {
    return ((uint32_t)*(uint16_t*)&a) | ((uint32_t)*(uint16_t*)&b << 16);
}

#define LDSM4(R0, R1, R2, R3, ADDR) \
    asm volatile("ldmatrix.sync.aligned.m8n8.x4.shared.b16 {%0,%1,%2,%3}, [%4];" \
                 : "=r"(R0), "=r"(R1), "=r"(R2), "=r"(R3) : "r"(ADDR))

#define MMA16816(d, a, b) asm volatile( \
    "mma.sync.aligned.m16n8k16.row.col.f32.bf16.bf16.f32 " \
    "{%0,%1,%2,%3},{%4,%5,%6,%7},{%8,%9},{%0,%1,%2,%3};\n" \
    : "+f"(d[0]), "+f"(d[1]), "+f"(d[2]), "+f"(d[3]) \
    : "r"(a[0]), "r"(a[1]), "r"(a[2]), "r"(a[3]), "r"(b[0]), "r"(b[1]))

// ---------------- rope tables ----------------
__global__ void ropetab_k() {
    int s = blockIdx.x, i = threadIdx.x;
    double freq = exp(-(double)i * (log(10000.0) / 32.0));
    double a = (double)s * freq;
    g_cos[s * 32 + i] = (float)cos(a);
    g_sin[s * 32 + i] = (float)sin(a);
}

// ---------------- embedding ----------------
__global__ void embed_k(const int* __restrict__ ids, const int* __restrict__ iter,
                        const float* __restrict__ emb, const float* __restrict__ iter_emb) {
    int t = blockIdx.x, d = threadIdx.x;
    int id = ids[t];
    float v = emb[(size_t)id * D_ + d];
    int it = iter[0];
    if (it < NLOOPS_) v += iter_emb[it * D_ + d];
    g_x[(size_t)t * D_ + d] = v;
}

// ---------------- weight conversion (gate/up interleaved) ----------------
__global__ void cvt_all_k(const float* __restrict__ Wqkv, const float* __restrict__ wo,
                          const float* __restrict__ gate, const float* __restrict__ up,
                          const float* __restrict__ down) {
    size_t i = (size_t)blockIdx.x * 256 + threadIdx.x;
    if (i >= WTOT) return;
    size_t l = i / LW, off = i % LW;
    const float* src; size_t so;
    if (off < WOFF_WO)      { src = Wqkv; so = l * 307200 + off; }
    else if (off < WOFF_GU) { src = wo;   so = l * 102400 + (off - WOFF_WO); }
    else if (off < WOFF_D)  {
        size_t idx = off - WOFF_GU;
        size_t row = idx / D_, col = idx % D_;
        size_t ff = row >> 1;
        src = (row & 1) ? up : gate;
        so = l * 276480 + ff * D_ + col;
    }
    else                    { src = down; so = l * 276480 + (off - WOFF_D); }
    float f = src[so];
    __nv_bfloat16 h, lo; split_bf(f, h, lo);
    g_whi[i] = h; g_wlo[i] = lo;
}

// ---------------- rmsnorm variants ----------------
__global__ void rmsnorm_k(const float* __restrict__ in, const float* __restrict__ w,
                          float* __restrict__ out, int nrows) {
    int warp = (blockIdx.x * blockDim.x + threadIdx.x) >> 5;
    int lane = threadIdx.x & 31;
    if (warp >= nrows) return;
    const float* r = in + (size_t)warp * D_;
    float e[10]; float ss = 0.f;
#pragma unroll
    for (int i = 0; i < 10; i++) { e[i] = r[lane + 32 * i]; ss += e[i] * e[i]; }
#pragma unroll
    for (int o = 16; o > 0; o >>= 1) ss += __shfl_xor_sync(0xffffffffu, ss, o);
    float rr = rsqrtf(ss * (1.0f / D_) + 1e-6f);
    float* po = out + (size_t)warp * D_;
#pragma unroll
    for (int i = 0; i < 10; i++) po[lane + 32 * i] = e[i] * rr * w[lane + 32 * i];
}

// also zeroes g_probs[row] for the fused-router atomic accumulation
__global__ void rmsnorm_bf_k(const float* __restrict__ in, const float* __restrict__ w,
                             __nv_bfloat16* __restrict__ ohi, __nv_bfloat16* __restrict__ olo,
                             int nrows) {
    int warp = (blockIdx.x * blockDim.x + threadIdx.x) >> 5;
    int lane = threadIdx.x & 31;
    if (warp >= nrows) return;
    if (lane == 0) g_probs[warp] = 0.f;
    const float* r = in + (size_t)warp * D_;
    float e[10]; float ss = 0.f;
#pragma unroll
    for (int i = 0; i < 10; i++) { e[i] = r[lane + 32 * i]; ss += e[i] * e[i]; }
#pragma unroll
    for (int o = 16; o > 0; o >>= 1) ss += __shfl_xor_sync(0xffffffffu, ss, o);
    float rr = rsqrtf(ss * (1.0f / D_) + 1e-6f);
#pragma unroll
    for (int i = 0; i < 10; i++) {
        float v = e[i] * rr * w[lane + 32 * i];
        __nv_bfloat16 h, l; split_bf(v, h, l);
        ohi[(size_t)warp * D_ + lane + 32 * i] = h;
        olo[(size_t)warp * D_ + lane + 32 * i] = l;
    }
}

__global__ void gather_rmsnorm_k(const float* __restrict__ in, const float* __restrict__ w,
                                 __nv_bfloat16* __restrict__ ohi, __nv_bfloat16* __restrict__ olo) {
    int warp = (blockIdx.x * blockDim.x + threadIdx.x) >> 5;
    int lane = threadIdx.x & 31;
    if (warp >= MS_) return;
    int b = warp / KSEL;
    int tok = g_selidx[warp];
    const float* r = in + (size_t)(b * S_ + tok) * D_;
    float e[10]; float ss = 0.f;
#pragma unroll
    for (int i = 0; i < 10; i++) { e[i] = r[lane + 32 * i]; ss += e[i] * e[i]; }
#pragma unroll
    for (int o = 16; o > 0; o >>= 1) ss += __shfl_xor_sync(0xffffffffu, ss, o);
    float rr = rsqrtf(ss * (1.0f / D_) + 1e-6f);
#pragma unroll
    for (int i = 0; i < 10; i++) {
        float v = e[i] * rr * w[lane + 32 * i];
        __nv_bfloat16 h, l; split_bf(v, h, l);
        ohi[(size_t)warp * D_ + lane + 32 * i] = h;
        olo[(size_t)warp * D_ + lane + 32 * i] = l;
    }
}

// =====================================================================
// bf16x3 tensor-core GEMM, templated on WN: BN = 64*WN.
// WN=2: 2-stage, occupancy 2. WN=1: 2-stage, occupancy 3.
// Term-major MMA ordering (dependency distance 4).
// epi: 0 store, 1 += C (+ fused router partial-dot if rw), 2 scatter-add,
//      3 fused qkv rope/scale/split/pack, 4 fused gate/up silu
// =====================================================================
template <int WN>
__global__ __launch_bounds__(256, (WN == 1) ? 3 : 2) void hgemm3_k(
    const __nv_bfloat16* __restrict__ Ahi, const __nv_bfloat16* __restrict__ Alo,
    const __nv_bfloat16* __restrict__ Bhi, const __nv_bfloat16* __restrict__ Blo,
    float* __restrict__ C, int M, int N, int K, int epi,
    const int* __restrict__ selidx, const float* __restrict__ selprob,
    float* __restrict__ xout, const float* __restrict__ rw) {
    extern __shared__ __nv_bfloat16 sm[];
    constexpr int BN  = 64 * WN;
    constexpr int MT  = WN;
    constexpr int ASZ = 128 * 40;
    constexpr int BSZ = BN * 40;
    constexpr int STG = 2 * ASZ + 2 * BSZ;

    const int tid = threadIdx.x;
    const int lane = tid & 31, warp = tid >> 5;
    const int wn = warp & (WN - 1);
    const int wm = warp / WN;
    const int bm = blockIdx.y * 128, bn = blockIdx.x * BN;

    float acc[MT][8][4];
#pragma unroll
    for (int a = 0; a < MT; a++)
#pragma unroll
        for (int b = 0; b < 8; b++)
#pragma unroll
            for (int c = 0; c < 4; c++) acc[a][b][c] = 0.f;

    uint32_t smemBase = (uint32_t)__cvta_generic_to_shared(sm);
    const int KT = K / 32;
    const int crow = tid >> 2, cseg = tid & 3;

    auto load_stage = [&](int kt, int s) {
        int k0 = kt * 32;
#pragma unroll
        for (int arr = 0; arr < 4; arr++) {
            const __nv_bfloat16* src = arr == 0 ? Ahi : arr == 1 ? Alo : arr == 2 ? Bhi : Blo;
            const bool isA = arr < 2;
            const int lim = isA ? M : N;
            const int gbase = isA ? bm : bn;
            const int nIter = isA ? 2 : BN / 64;
            const uint32_t abase = (arr < 2) ? (uint32_t)(arr * ASZ)
                                             : (uint32_t)(2 * ASZ + (arr - 2) * BSZ);
#pragma unroll
            for (int i = 0; i < 2; i++) {
                if (i >= nIter) break;
                int row = crow + i * 64;
                int g = gbase + row;
                const __nv_bfloat16* gp = src + (size_t)g * K + k0 + cseg * 8;
                uint32_t dst = smemBase + (uint32_t)(s * STG + abase + row * 40 + cseg * 8) * 2u;
                int sz = (g < lim) ? 16 : 0;
                asm volatile("cp.async.cg.shared.global [%0], [%1], 16, %2;\n"
                             :: "r"(dst), "l"(gp), "r"(sz));
            }
        }
        asm volatile("cp.async.commit_group;\n");
    };

    const uint32_t arow = ((lane >> 3) & 1) * 8 + (lane & 7);
    const uint32_t acolo = (lane >> 4) * 8;
    const uint32_t brow = (lane >> 4) * 8 + (lane & 7);
    const uint32_t bcolo = ((lane >> 3) & 1) * 8;

    auto compute = [&](int s) {
        const uint32_t base = smemBase + (uint32_t)(s * STG) * 2u;
#pragma unroll
        for (int kk = 0; kk < 2; kk++) {
            const uint32_t k0 = kk * 16;
            uint32_t ah[MT][4], al[MT][4];
#pragma unroll
            for (int mt = 0; mt < MT; mt++) {
                uint32_t aoff = (uint32_t)((wm * 16 * MT + mt * 16 + arow) * 40 + k0 + acolo) * 2u;
                LDSM4(ah[mt][0], ah[mt][1], ah[mt][2], ah[mt][3], base + aoff);
                LDSM4(al[mt][0], al[mt][1], al[mt][2], al[mt][3], base + ASZ * 2u + aoff);
            }
#pragma unroll
            for (int p = 0; p < 4; p++) {
                uint32_t boff = (uint32_t)((wn * 64 + p * 16 + brow) * 40 + k0 + bcolo) * 2u;
                uint32_t bhf[2][2], blf[2][2];
                LDSM4(bhf[0][0], bhf[0][1], bhf[1][0], bhf[1][1], base + 2u * ASZ * 2u + boff);
                LDSM4(blf[0][0], blf[0][1], blf[1][0], blf[1][1],
                      base + (2u * ASZ + BSZ) * 2u + boff);
                // term-major: dependency distance = 2*MT independent accs per term
#pragma unroll
                for (int q = 0; q < 2; q++)
#pragma unroll
                    for (int mt = 0; mt < MT; mt++)
                        MMA16816(acc[mt][2 * p + q], ah[mt], bhf[q]);
#pragma unroll
                for (int q = 0; q < 2; q++)
#pragma unroll
                    for (int mt = 0; mt < MT; mt++)
                        MMA16816(acc[mt][2 * p + q], ah[mt], blf[q]);
#pragma unroll
                for (int q = 0; q < 2; q++)
#pragma unroll
                    for (int mt = 0; mt < MT; mt++)
                        MMA16816(acc[mt][2 * p + q], al[mt], bhf[q]);
            }
        }
    };

    load_stage(0, 0);
    if (KT > 1) load_stage(1, 1);
    for (int kt = 0; kt < KT; kt++) {
        const int s = kt & 1;
        if (kt + 1 < KT) asm volatile("cp.async.wait_group 1;\n");
        else             asm volatile("cp.async.wait_group 0;\n");
        __syncthreads();
        compute(s);
        __syncthreads();
        if (kt + 2 < KT) load_stage(kt + 2, s);
    }

    // ---------------- epilogues ----------------
    if (epi == 3) {
        int nb = (bn + wn * 64) >> 6;
        if (nb < 15) {
            int region = nb / 5, hd = nb % 5;
#pragma unroll
            for (int mt = 0; mt < MT; mt++) {
#pragma unroll
                for (int ci = 0; ci < 2; ci++) {
                    int m = bm + wm * 16 * MT + mt * 16 + (lane >> 2) + ci * 8;
                    if (m >= M) continue;
                    int b = m / S_, s = m - b * S_;
                    size_t bh_ = (size_t)(b * NH_ + hd);
                    if (region < 2) {
                        const float qsc = region ? 1.f : 0.125f;
                        __nv_bfloat16* dh = (region ? g_kh : g_qh) + (bh_ * S_ + s) * HD_;
                        __nv_bfloat16* dl = (region ? g_kl : g_ql) + (bh_ * S_ + s) * HD_;
#pragma unroll
                        for (int nt = 0; nt < 4; nt++) {
                            int d0 = nt * 8 + (lane & 3) * 2;
                            float r1[2], r2[2];
#pragma unroll
                            for (int j = 0; j < 2; j++) {
                                int dd = d0 + j;
                                float v1 = acc[mt][nt][ci * 2 + j];
                                float v2 = acc[mt][nt + 4][ci * 2 + j];
                                float co = g_cos[s * 32 + dd];
                                float si = g_sin[s * 32 + dd];
                                r1[j] = (v1 * co - v2 * si) * qsc;
                                r2[j] = (v2 * co + v1 * si) * qsc;
                            }
                            __nv_bfloat16 h0, l0, h1, l1;
                            split_bf(r1[0], h0, l0); split_bf(r1[1], h1, l1);
                            *(uint32_t*)(dh + d0) = pack2(h0, h1);
                            *(uint32_t*)(dl + d0) = pack2(l0, l1);
                            split_bf(r2[0], h0, l0); split_bf(r2[1], h1, l1);
                            *(uint32_t*)(dh + d0 + 32) = pack2(h0, h1);
                            *(uint32_t*)(dl + d0 + 32) = pack2(l0, l1);
                        }
                    } else {
#pragma unroll
                        for (int nt = 0; nt < 8; nt++) {
#pragma unroll
                            for (int j = 0; j < 2; j++) {
                                int d = nt * 8 + (lane & 3) * 2 + j;
                                float v = acc[mt][nt][ci * 2 + j];
                                __nv_bfloat16 hh, ll; split_bf(v, hh, ll);
                                size_t idx = (bh_ * HD_ + d) * S_ + s;
                                g_vth[idx] = hh;
                                g_vtl[idx] = ll;
                            }
                        }
                    }
                }
            }
        }
    } else if (epi == 4) {
#pragma unroll
        for (int mt = 0; mt < MT; mt++) {
#pragma unroll
            for (int ci = 0; ci < 2; ci++) {
                int m = bm + wm * 16 * MT + mt * 16 + (lane >> 2) + ci * 8;
                if (m >= M) continue;
#pragma unroll
                for (int nt = 0; nt < 8; nt++) {
                    int n = bn + wn * 64 + nt * 8 + (lane & 3) * 2;
                    if (n + 1 < N) {
                        float gv = acc[mt][nt][ci * 2 + 0];
                        float uv = acc[mt][nt][ci * 2 + 1];
                        float v = gv / (1.f + __expf(-gv)) * uv;
                        int ff = n >> 1;
                        __nv_bfloat16 h, l; split_bf(v, h, l);
                        g_acthi[(size_t)m * FF_ + ff] = h;
                        g_actlo[(size_t)m * FF_ + ff] = l;
                    }
                }
            }
        }
    } else {
#pragma unroll
        for (int mt = 0; mt < MT; mt++) {
#pragma unroll
            for (int ci = 0; ci < 2; ci++) {
                int m = bm + wm * 16 * MT + mt * 16 + (lane >> 2) + ci * 8;
                if (m >= M) continue;
                int xrow = 0; float sc = 0.f;
                if (epi == 2) { xrow = (m / KSEL) * S_ + selidx[m]; sc = selprob[m]; }
                float zp = 0.f;
#pragma unroll
                for (int nt = 0; nt < 8; nt++) {
                    int n = bn + wn * 64 + nt * 8 + (lane & 3) * 2;
                    float v0 = acc[mt][nt][ci * 2 + 0];
                    float v1 = acc[mt][nt][ci * 2 + 1];
                    if (n + 1 < N) {
                        if (epi == 0) {
                            *(float2*)(C + (size_t)m * N + n) = make_float2(v0, v1);
                        } else if (epi == 1) {
                            float2 c = *(float2*)(C + (size_t)m * N + n);
                            c.x += v0; c.y += v1;
                            *(float2*)(C + (size_t)m * N + n) = c;
                            if (rw) {
                                float2 w2 = *(const float2*)(rw + n);
                                zp += c.x * w2.x + c.y * w2.y;
                            }
                        } else {
                            float2 c = *(float2*)(xout + (size_t)xrow * D_ + n);
                            c.x += v0 * sc; c.y += v1 * sc;
                            *(float2*)(xout + (size_t)xrow * D_ + n) = c;
                        }
                    } else if (n < N) {
                        if (epi == 0) C[(size_t)m * N + n] = v0;
                        else if (epi == 1) C[(size_t)m * N + n] += v0;
                        else xout[(size_t)xrow * D_ + n] += v0 * sc;
                    }
                }
                if (epi == 1 && rw) {
                    zp += __shfl_xor_sync(0xffffffffu, zp, 1);
                    zp += __shfl_xor_sync(0xffffffffu, zp, 2);
                    if ((lane & 3) == 0) atomicAdd(&g_probs[m], zp);
                }
            }
        }
    }
}

// =====================================================================
// tensor-core flash attention: 256 threads, 128-row qtiles, heavy-first,
// 3-stage cp.async with ONE __syncthreads per tile. Term-major MMAs.
// =====================================================================
__global__ __launch_bounds__(256, 1) void attn_tc_k() {
    extern __shared__ __nv_bfloat16 asm_[];
    constexpr int RP = 72;
    constexpr int TSZ = 64 * RP;
    constexpr int STG = 4 * TSZ;

    const int bh = blockIdx.x;
    const int qtile = (S_ / 128 - 1) - blockIdx.y;   // heavy tiles first
    const int b = bh / NH_, h = bh % NH_;
    const int tid = threadIdx.x, lane = tid & 31, warp = tid >> 5;
    const int q0 = qtile * 128 + warp * 16;
    const int r1 = lane >> 2, c0 = (lane & 3) * 2;

    uint32_t qh[4][4], ql[4][4];
    {
        const __nv_bfloat16* Qh = g_qh + ((size_t)bh * S_ + q0) * HD_;
        const __nv_bfloat16* Ql = g_ql + ((size_t)bh * S_ + q0) * HD_;
#pragma unroll
        for (int ks = 0; ks < 4; ks++) {
            int kc = ks * 16 + c0;
            qh[ks][0] = *(const uint32_t*)(Qh + r1 * 64 + kc);
            qh[ks][1] = *(const uint32_t*)(Qh + (r1 + 8) * 64 + kc);
            qh[ks][2] = *(const uint32_t*)(Qh + r1 * 64 + kc + 8);
            qh[ks][3] = *(const uint32_t*)(Qh + (r1 + 8) * 64 + kc + 8);
            ql[ks][0] = *(const uint32_t*)(Ql + r1 * 64 + kc);
            ql[ks][1] = *(const uint32_t*)(Ql + (r1 + 8) * 64 + kc);
            ql[ks][2] = *(const uint32_t*)(Ql + r1 * 64 + kc + 8);
            ql[ks][3] = *(const uint32_t*)(Ql + (r1 + 8) * 64 + kc + 8);
        }
    }

    float oacc[8][4];
#pragma unroll
    for (int i = 0; i < 8; i++)
#pragma unroll
        for (int j = 0; j < 4; j++) oacc[i][j] = 0.f;
    float m1 = -1e30f, m2 = -1e30f, l1 = 0.f, l2 = 0.f;

    uint32_t smemBase = (uint32_t)__cvta_generic_to_shared(asm_);
    const int NT = 2 * qtile + 2;
    const int lrow = tid >> 2, lch = tid & 3;
    const uint32_t frow = (lane >> 4) * 8 + (lane & 7);
    const uint32_t fcolo = ((lane >> 3) & 1) * 8;

    auto load_tile = [&](int kt, int st) {
        int k0 = kt * 64;
        const __nv_bfloat16* srcs[4] = {
            g_kh + ((size_t)bh * S_ + k0) * HD_,
            g_kl + ((size_t)bh * S_ + k0) * HD_,
            g_vth + (size_t)bh * HD_ * S_ + k0,
            g_vtl + (size_t)bh * HD_ * S_ + k0};
        const size_t rstride[4] = {HD_, HD_, S_, S_};
#pragma unroll
        for (int arr = 0; arr < 4; arr++) {
#pragma unroll
            for (int i = 0; i < 2; i++) {
                int ch = lch + i * 4;
                const __nv_bfloat16* gp = srcs[arr] + (size_t)lrow * rstride[arr] + ch * 8;
                uint32_t dst = smemBase + (uint32_t)(st * STG + arr * TSZ + lrow * RP + ch * 8) * 2u;
                asm volatile("cp.async.cg.shared.global [%0], [%1], 16;\n" :: "r"(dst), "l"(gp));
            }
        }
        asm volatile("cp.async.commit_group;\n");
    };

    load_tile(0, 0);
    if (NT > 1) load_tile(1, 1);
    for (int kt = 0; kt < NT; kt++) {
        if (kt + 1 < NT) asm volatile("cp.async.wait_group 1;\n");
        else             asm volatile("cp.async.wait_group 0;\n");
        __syncthreads();
        if (kt + 2 < NT) load_tile(kt + 2, (kt + 2) % 3);
        const int k0 = kt * 64;
        if (k0 <= q0 + 15) {
            const int st = kt % 3;
            const uint32_t kbase_h = smemBase + (uint32_t)(st * STG) * 2u;
            const uint32_t kbase_l = kbase_h + (uint32_t)TSZ * 2u;
            const uint32_t vbase_h = kbase_h + 2u * (uint32_t)TSZ * 2u;
            const uint32_t vbase_l = kbase_h + 3u * (uint32_t)TSZ * 2u;

            float sacc[8][4];
#pragma unroll
            for (int i = 0; i < 8; i++)
#pragma unroll
                for (int j = 0; j < 4; j++) sacc[i][j] = 0.f;

#pragma unroll
            for (int ks = 0; ks < 4; ks++) {
                const uint32_t kc = ks * 16 + fcolo;
#pragma unroll
                for (int p = 0; p < 2; p++) {
                    // load two p-groups: 4 independent accumulators per term
                    uint32_t boff0 = (uint32_t)(((2 * p) * 16 + frow) * RP + kc) * 2u;
                    uint32_t boff1 = (uint32_t)(((2 * p + 1) * 16 + frow) * RP + kc) * 2u;
                    uint32_t kh4[4][2], kl4[4][2];
                    LDSM4(kh4[0][0], kh4[0][1], kh4[1][0], kh4[1][1], kbase_h + boff0);
                    LDSM4(kh4[2][0], kh4[2][1], kh4[3][0], kh4[3][1], kbase_h + boff1);
                    LDSM4(kl4[0][0], kl4[0][1], kl4[1][0], kl4[1][1], kbase_l + boff0);
                    LDSM4(kl4[2][0], kl4[2][1], kl4[3][0], kl4[3][1], kbase_l + boff1);
#pragma unroll
                    for (int q = 0; q < 4; q++) MMA16816(sacc[4 * p + q], qh[ks], kh4[q]);
#pragma unroll
                    for (int q = 0; q < 4; q++) MMA16816(sacc[4 * p + q], qh[ks], kl4[q]);
#pragma unroll
                    for (int q = 0; q < 4; q++) MMA16816(sacc[4 * p + q], ql[ks], kh4[q]);
                }
            }
            const bool diag = (k0 + 63 > q0);
            if (diag) {
#pragma unroll
                for (int nt = 0; nt < 8; nt++) {
#pragma unroll
                    for (int j = 0; j < 4; j++) {
                        int col = k0 + nt * 8 + c0 + (j & 1);
                        int row = q0 + r1 + ((j >= 2) ? 8 : 0);
                        if (col > row) sacc[nt][j] = -1e30f;
                    }
                }
            }
            float t1 = -1e30f, t2 = -1e30f;
#pragma unroll
            for (int nt = 0; nt < 8; nt++) {
                t1 = fmaxf(t1, fmaxf(sacc[nt][0], sacc[nt][1]));
                t2 = fmaxf(t2, fmaxf(sacc[nt][2], sacc[nt][3]));
            }
            t1 = fmaxf(t1, __shfl_xor_sync(0xffffffffu, t1, 1));
            t1 = fmaxf(t1, __shfl_xor_sync(0xffffffffu, t1, 2));
            t2 = fmaxf(t2, __shfl_xor_sync(0xffffffffu, t2, 1));
            t2 = fmaxf(t2, __shfl_xor_sync(0xffffffffu, t2, 2));
            float nm1 = fmaxf(m1, t1), nm2 = fmaxf(m2, t2);
            float cc1 = __expf(m1 - nm1), cc2 = __expf(m2 - nm2);
            l1 *= cc1; l2 *= cc2;
#pragma unroll
            for (int nt = 0; nt < 8; nt++) {
                oacc[nt][0] *= cc1; oacc[nt][1] *= cc1;
                oacc[nt][2] *= cc2; oacc[nt][3] *= cc2;
            }
            m1 = nm1; m2 = nm2;
            float rs1 = 0.f, rs2 = 0.f;
#pragma unroll
            for (int nt = 0; nt < 8; nt++) {
                sacc[nt][0] = __expf(sacc[nt][0] - nm1); rs1 += sacc[nt][0];
                sacc[nt][1] = __expf(sacc[nt][1] - nm1); rs1 += sacc[nt][1];
                sacc[nt][2] = __expf(sacc[nt][2] - nm2); rs2 += sacc[nt][2];
                sacc[nt][3] = __expf(sacc[nt][3] - nm2); rs2 += sacc[nt][3];
            }
            rs1 += __shfl_xor_sync(0xffffffffu, rs1, 1);
            rs1 += __shfl_xor_sync(0xffffffffu, rs1, 2);
            rs2 += __shfl_xor_sync(0xffffffffu, rs2, 1);
            rs2 += __shfl_xor_sync(0xffffffffu, rs2, 2);
            l1 += rs1; l2 += rs2;
            uint32_t pa[4][4], pl[4][4];
#pragma unroll
            for (int kp = 0; kp < 4; kp++) {
                int n0 = 2 * kp, n1 = 2 * kp + 1;
#define PPACK(dsti, x0, x1) { \
                float a0 = (x0), a1 = (x1); \
                __nv_bfloat16 b0 = __float2bfloat16(a0), b1 = __float2bfloat16(a1); \
                pa[kp][dsti] = ((uint32_t)*(uint16_t*)&b0) | ((uint32_t)*(uint16_t*)&b1 << 16); \
                float r0 = a0 - __bfloat162float(b0), r1f = a1 - __bfloat162float(b1); \
                __nv_bfloat16 c0b = __float2bfloat16(r0), c1b = __float2bfloat16(r1f); \
                pl[kp][dsti] = ((uint32_t)*(uint16_t*)&c0b) | ((uint32_t)*(uint16_t*)&c1b << 16); }
                PPACK(0, sacc[n0][0], sacc[n0][1]);
                PPACK(1, sacc[n0][2], sacc[n0][3]);
                PPACK(2, sacc[n1][0], sacc[n1][1]);
                PPACK(3, sacc[n1][2], sacc[n1][3]);
#undef PPACK
            }
#pragma unroll
            for (int kp = 0; kp < 4; kp++) {
                const uint32_t kc = kp * 16 + fcolo;
#pragma unroll
                for (int p = 0; p < 2; p++) {
                    uint32_t boff0 = (uint32_t)(((2 * p) * 16 + frow) * RP + kc) * 2u;
                    uint32_t boff1 = (uint32_t)(((2 * p + 1) * 16 + frow) * RP + kc) * 2u;
                    uint32_t vh4[4][2], vl4[4][2];
                    LDSM4(vh4[0][0], vh4[0][1], vh4[1][0], vh4[1][1], vbase_h + boff0);
                    LDSM4(vh4[2][0], vh4[2][1], vh4[3][0], vh4[3][1], vbase_h + boff1);
                    LDSM4(vl4[0][0], vl4[0][1], vl4[1][0], vl4[1][1], vbase_l + boff0);
                    LDSM4(vl4[2][0], vl4[2][1], vl4[3][0], vl4[3][1], vbase_l + boff1);
#pragma unroll
                    for (int q = 0; q < 4; q++) MMA16816(oacc[4 * p + q], pa[kp], vh4[q]);
#pragma unroll
                    for (int q = 0; q < 4; q++) MMA16816(oacc[4 * p + q], pa[kp], vl4[q]);
#pragma unroll
                    for (int q = 0; q < 4; q++) MMA16816(oacc[4 * p + q], pl[kp], vh4[q]);
                }
            }
        }
    }

    float inv1 = 1.f / l1, inv2 = 1.f / l2;
    int row1 = b * S_ + q0 + r1;
    int row2 = row1 + 8;
#pragma unroll
    for (int nt = 0; nt < 8; nt++) {
        int col = h * HD_ + nt * 8 + c0;
        {
            float v0 = oacc[nt][0] * inv1, v1 = oacc[nt][1] * inv1;
            __nv_bfloat16 h0, l0, h1v, l1v;
            split_bf(v0, h0, l0); split_bf(v1, h1v, l1v);
            *(uint32_t*)(g_athi + (size_t)row1 * D_ + col) = pack2(h0, h1v);
            *(uint32_t*)(g_atlo + (size_t)row1 * D_ + col) = pack2(l0, l1v);
        }
        {
            float v0 = oacc[nt][2] * inv2, v1 = oacc[nt][3] * inv2;
            __nv_bfloat16 h0, l0, h1v, l1v;
            split_bf(v0, h0, l0); split_bf(v1, h1v, l1v);
            *(uint32_t*)(g_athi + (size_t)row2 * D_ + col) = pack2(h0, h1v);
            *(uint32_t*)(g_atlo + (size_t)row2 * D_ + col) = pack2(l0, l1v);
        }
    }
}

// ---------------- exact top-k (z -> sigmoid, monotonic), 1024 threads ----------------
__global__ __launch_bounds__(1024) void topk_k() {
    int b = blockIdx.x;
    __shared__ float p[S_];
    for (int i = threadIdx.x; i < S_; i += 1024) {
        float z = g_probs[b * S_ + i];
        p[i] = 1.f / (1.f + __expf(-z));
    }
    __syncthreads();
    int idx[2]; float v[2]; int cnt[2];
#pragma unroll
    for (int t = 0; t < 2; t++) {
        idx[t] = threadIdx.x + t * 1024;
        v[t] = p[idx[t]];
        cnt[t] = 0;
    }
    for (int j = 0; j < S_; j++) {
        float pj = p[j];
#pragma unroll
        for (int t = 0; t < 2; t++)
            cnt[t] += (pj > v[t]) || (pj == v[t] && j < idx[t]) ? 1 : 0;
    }
#pragma unroll
    for (int t = 0; t < 2; t++) {
        if (cnt[t] < KSEL) {
            g_selidx[b * KSEL + cnt[t]] = idx[t];
            g_selprob[b * KSEL + cnt[t]] = v[t];
        }
    }
}

// ---------------- host launch ----------------
extern "C" void kernel_launch(void* const* d_in, const int* in_sizes, int n_in,
                              void* d_out, int out_size) {
    const int* ids            = (const int*)d_in[0];
    const int* iter           = (const int*)d_in[1];
    const float* emb          = (const float*)d_in[2];
    const float* iter_emb     = (const float*)d_in[3];
    const float* attn_norm_w  = (const float*)d_in[4];
    const float* Wqkv         = (const float*)d_in[5];
    const float* wo_w         = (const float*)d_in[6];
    const float* router_w     = (const float*)d_in[7];
    const float* mlp_norm_w   = (const float*)d_in[8];
    const float* gate_w       = (const float*)d_in[9];
    const float* up_w         = (const float*)d_in[10];
    const float* down_w       = (const float*)d_in[11];
    const float* final_norm_w = (const float*)d_in[12];
    float* out = (float*)d_out;

    float *px, *pselprob;
    int* pselidx;
    __nv_bfloat16 *pwhi, *pwlo, *phhi, *phlo, *pathi, *patlo, *phshi, *phslo, *pacthi, *pactlo;
    cudaGetSymbolAddress((void**)&px, g_x);
    cudaGetSymbolAddress((void**)&pselidx, g_selidx);
    cudaGetSymbolAddress((void**)&pselprob, g_selprob);
    cudaGetSymbolAddress((void**)&pwhi, g_whi);
    cudaGetSymbolAddress((void**)&pwlo, g_wlo);
    cudaGetSymbolAddress((void**)&phhi, g_hhi);
    cudaGetSymbolAddress((void**)&phlo, g_hlo);
    cudaGetSymbolAddress((void**)&pathi, g_athi);
    cudaGetSymbolAddress((void**)&patlo, g_atlo);
    cudaGetSymbolAddress((void**)&phshi, g_hshi);
    cudaGetSymbolAddress((void**)&phslo, g_hslo);
    cudaGetSymbolAddress((void**)&pacthi, g_acthi);
    cudaGetSymbolAddress((void**)&pactlo, g_actlo);

    constexpr int SMEM_G2 = 2 * (2 * 128 * 40 + 2 * 128 * 40) * 2;  // 81920 B (WN=2, occ 2)
    constexpr int SMEM_G1 = 2 * (2 * 128 * 40 + 2 * 64 * 40) * 2;   // 61440 B (WN=1, occ 3)
    constexpr int SMEM_ATTN = 3 * 4 * 64 * 72 * 2;                  // 110592 B (3 stages)
    cudaFuncSetAttribute(hgemm3_k<2>, cudaFuncAttributeMaxDynamicSharedMemorySize, SMEM_G2);
    cudaFuncSetAttribute(hgemm3_k<1>, cudaFuncAttributeMaxDynamicSharedMemorySize, SMEM_G1);
    cudaFuncSetAttribute(attn_tc_k, cudaFuncAttributeMaxDynamicSharedMemorySize, SMEM_ATTN);

    ropetab_k<<<S_, 32>>>();
    embed_k<<<T_, D_>>>(ids, iter, emb, iter_emb);
    cvt_all_k<<<(int)((WTOT + 255) / 256), 256>>>(Wqkv, wo_w, gate_w, up_w, down_w);

    const int MT  = T_ / 128;                 // 128
    const int MTS = (MS_ + 127) / 128;        // 103

    for (int l = 0; l < NL_; l++) {
        size_t lo = (size_t)l * LW;

        rmsnorm_bf_k<<<T_ / 4, 128>>>(px, attn_norm_w + l * D_, phhi, phlo, T_);
        // qkv GEMM with fused rope/scale/split/pack epilogue (WN=2)
        {
            dim3 g((3 * D_ + 127) / 128, MT);
            hgemm3_k<2><<<g, 256, SMEM_G2>>>(phhi, phlo, pwhi + lo + WOFF_QKV, pwlo + lo + WOFF_QKV,
                                             nullptr, T_, 3 * D_, D_, 3, nullptr, nullptr, nullptr,
                                             nullptr);
        }
        {
            dim3 g(B_ * NH_, S_ / 128);
            attn_tc_k<<<g, 256, SMEM_ATTN>>>();
        }
        // x += attn @ wo^T, fused router partial-dot (WN=1, occ 3)
        {
            dim3 g((D_ + 63) / 64, MT);
            hgemm3_k<1><<<g, 256, SMEM_G1>>>(pathi, patlo, pwhi + lo + WOFF_WO, pwlo + lo + WOFF_WO,
                                             px, T_, D_, D_, 1, nullptr, nullptr, nullptr,
                                             router_w + l * D_);
        }
        topk_k<<<B_, 1024>>>();
        gather_rmsnorm_k<<<(MS_ + 3) / 4, 128>>>(px, mlp_norm_w + l * D_, phshi, phslo);
        // fused gate+up GEMM (interleaved N=1728) with silu*up epilogue (WN=2)
        {
            dim3 g((2 * FF_ + 127) / 128, MTS);
            hgemm3_k<2><<<g, 256, SMEM_G2>>>(phshi, phslo, pwhi + lo + WOFF_GU, pwlo + lo + WOFF_GU,
                                             nullptr, MS_, 2 * FF_, D_, 4, nullptr, nullptr, nullptr,
                                             nullptr);
        }
        // x[sel] += (act @ down^T) * prob (WN=1, occ 3)
        {
            dim3 g((D_ + 63) / 64, MTS);
            hgemm3_k<1><<<g, 256, SMEM_G1>>>(pacthi, pactlo, pwhi + lo + WOFF_D, pwlo + lo + WOFF_D,
                                             nullptr, MS_, D_, FF_, 2, pselidx, pselprob, px,
                                             nullptr);
        }
    }

    rmsnorm_k<<<T_ / 4, 128>>>(px, final_norm_w, out, T_);
}